// round 14
// baseline (speedup 1.0000x reference)
#include <cuda_runtime.h>
#include <cuda_fp16.h>
#include <cstdint>

#define B_   32
#define T_   256
#define N_   4096
#define D_   256
#define M_   (B_ * T_)
#define EPSF 1e-6f
#define DECF 0.97f

// ---------------- scratch (device globals; no allocation) ----------------
__device__ float g_CS[M_];
__device__ float g_Cc[M_];
__device__ float g_U [M_ * D_];
__device__ float g_S [2LL * B_ * T_ * T_];      // 2 split-K partials of 65536*scores
__device__ float g_A [2LL * M_ * D_];           // 2 split-K partials of a*
__device__ float g_O [2LL * M_ * D_];           // 2 split-K partials of G3
__device__ float g_DEC[T_];                     // 0.97^L / 65536 (gemm_nn only)

// fp16 operands; scalings: v,Dx x16; Dy,E x64; P,x x256; y x1024
__device__ __half g_Vf [M_ * D_];                             // 16*emb[idx]
__device__ __half g_DxH[N_ * D_];                             // 16*Dx
__device__ __half g_DyH[N_ * D_];                             // 64*Dy
__device__ __half g_EH [D_ * N_];                             // 64*E
__device__ __half g_Af [M_ * D_];                             // LN(a*) fp16
__device__ __half g_Xf [(long long)M_ * N_];                  // 256*x fp16
__device__ __half g_Yf [(long long)M_ * N_];                  // 256*P, then 1024*y fp16

// ---------------- PTX helpers (baseline ISA only) ----------------
__device__ __forceinline__ uint32_t smem_u32(const void* p) {
    uint32_t a;
    asm("{ .reg .u64 t; cvta.to.shared.u64 t, %1; cvt.u32.u64 %0, t; }" : "=r"(a) : "l"(p));
    return a;
}
__device__ __forceinline__ void cp16(uint32_t so, const void* g) {
    asm volatile("cp.async.cg.shared.global [%0], [%1], 16;" :: "r"(so), "l"(g));
}
__device__ __forceinline__ void cp_commit() {
    asm volatile("cp.async.commit_group;" ::: "memory");
}
template <int NN>
__device__ __forceinline__ void cp_wait() {
    asm volatile("cp.async.wait_group %0;" :: "n"(NN) : "memory");
}
__device__ __forceinline__ void ldsm_x4(uint32_t* f, uint32_t a) {
    asm volatile("ldmatrix.sync.aligned.m8n8.x4.shared.b16 {%0,%1,%2,%3}, [%4];"
        : "=r"(f[0]), "=r"(f[1]), "=r"(f[2]), "=r"(f[3]) : "r"(a));
}
__device__ __forceinline__ void mma_f16(float* c, const uint32_t* a, const uint32_t* b) {
    asm volatile("mma.sync.aligned.m16n8k16.row.col.f32.f16.f16.f32 "
        "{%0,%1,%2,%3}, {%4,%5,%6,%7}, {%8,%9}, {%0,%1,%2,%3};"
        : "+f"(c[0]), "+f"(c[1]), "+f"(c[2]), "+f"(c[3])
        : "r"(a[0]), "r"(a[1]), "r"(a[2]), "r"(a[3]), "r"(b[0]), "r"(b[1]));
}

// -- Main HMMA NT GEMM: CTA 128x256, warp 64x64, cross-chunk fragment pipelining
enum { EPI_NONE = 0, EPI_RELUH = 1, EPI_RELUMULX = 2 };

// swizzled tiles, 64B rows; phys 16B-slot = g ^ ((r>>1)&3)
#define TILE_A  8192                 // 128 rows x 64B
#define TILE_BT 16384                // 256 rows x 64B
#define STAGE_B (TILE_A + TILE_BT)   // 24576
#define NSTG    4
#define SMEM_SZ (NSTG * STAGE_B)     // 98304

template <int EPI>
__global__ void __launch_bounds__(256, 1) mma_nt(
    const __half* __restrict__ Ah, const __half* __restrict__ Bh,
    float* __restrict__ Cf, __half* __restrict__ Ch,
    const __half* __restrict__ Xf,
    int Nd, int K, int kLen, long sA, long sB, long sC, long splitStride, int batches)
{
    extern __shared__ char smem[];
    const uint32_t sb = smem_u32(smem);
    const int tid  = threadIdx.x;
    const int lane = tid & 31;
    const int wid  = tid >> 5;
    const int wm   = wid >> 2;
    const int wn   = wid & 3;
    const int zz   = blockIdx.z;
    const int split = zz / batches;
    const int bz    = zz - split * batches;
    const long kOff = (long)split * kLen;
    const int bm = blockIdx.y * 128;
    const int bn = blockIdx.x * 256;

    float acc[4][8][4];
#pragma unroll
    for (int i = 0; i < 4; i++)
#pragma unroll
        for (int j = 0; j < 8; j++)
#pragma unroll
            for (int v = 0; v < 4; v++) acc[i][j][v] = 0.f;

    {
        const __half* Ahp = Ah + (long)bz * sA + (long)bm * K + kOff;
        const __half* Bhp = Bh + (long)bz * sB + (long)bn * K + kOff;

        const int qr0 = tid >> 2;
        const int qc0 = tid & 3;
        auto stage_load = [&](int stg, int k0) {
            uint32_t base = sb + stg * STAGE_B;
#pragma unroll
            for (int i = 0; i < 2; i++) {
                int r = qr0 + i * 64;
                uint32_t so = (uint32_t)(r * 64 + ((qc0 ^ ((r >> 1) & 3)) * 16));
                cp16(base + so, Ahp + (long)r * K + k0 + qc0 * 8);
            }
#pragma unroll
            for (int i = 0; i < 4; i++) {
                int r = qr0 + i * 64;
                uint32_t so = (uint32_t)(r * 64 + ((qc0 ^ ((r >> 1) & 3)) * 16));
                cp16(base + TILE_A + so, Bhp + (long)r * K + k0 + qc0 * 8);
            }
            cp_commit();
        };

        const int nC = kLen / 32;
        stage_load(0, 0);
        stage_load(1, 32);
        stage_load(2, 64);

        const uint32_t aRow  = (uint32_t)(wm * 64 + (lane & 15));
        const uint32_t aColG = (uint32_t)(lane >> 4);
        const uint32_t bRow  = (uint32_t)(wn * 64 + ((lane >> 4) << 3) + (lane & 7));
        const uint32_t bColG = (uint32_t)((lane >> 3) & 1);
        const uint32_t sa  = (aRow >> 1) & 3;
        const uint32_t sbw = (bRow >> 1) & 3;
        uint32_t aoff[2], boff[2];
#pragma unroll
        for (int ks = 0; ks < 2; ks++) {
            aoff[ks] = aRow * 64 + (((ks * 2 + aColG) ^ sa) * 16);
            boff[ks] = bRow * 64 + (((ks * 2 + bColG) ^ sbw) * 16);
        }

        uint32_t fA0[4][4], fB0[4][4], fA1[4][4], fB1[4][4];

        cp_wait<2>();
        __syncthreads();
#pragma unroll
        for (int ma = 0; ma < 4; ma++)
            ldsm_x4(fA0[ma], sb + aoff[0] + ma * 1024);
#pragma unroll
        for (int p = 0; p < 4; p++)
            ldsm_x4(fB0[p], sb + TILE_A + boff[0] + p * 1024);

        int stg = 0;
        for (int c = 0; c < nC; c++) {
            __syncthreads();
            if (c + 3 < nC) {
                int ns = stg + 3; if (ns >= NSTG) ns -= NSTG;
                stage_load(ns, (c + 3) * 32);
            } else {
                cp_commit();
            }

            const uint32_t st = sb + stg * STAGE_B;
#pragma unroll
            for (int ma = 0; ma < 4; ma++)
                ldsm_x4(fA1[ma], st + aoff[1] + ma * 1024);
#pragma unroll
            for (int p = 0; p < 4; p++)
                ldsm_x4(fB1[p], st + TILE_A + boff[1] + p * 1024);
#pragma unroll
            for (int ma = 0; ma < 4; ma++)
#pragma unroll
                for (int na = 0; na < 8; na++)
                    mma_f16(acc[ma][na], fA0[ma], &fB0[na >> 1][2 * (na & 1)]);

            cp_wait<2>();
            int nstg = stg + 1; if (nstg >= NSTG) nstg = 0;
            if (c + 1 < nC) {
                const uint32_t st2 = sb + nstg * STAGE_B;
#pragma unroll
                for (int ma = 0; ma < 4; ma++)
                    ldsm_x4(fA0[ma], st2 + aoff[0] + ma * 1024);
#pragma unroll
                for (int p = 0; p < 4; p++)
                    ldsm_x4(fB0[p], st2 + TILE_A + boff[0] + p * 1024);
            }
#pragma unroll
            for (int ma = 0; ma < 4; ma++)
#pragma unroll
                for (int na = 0; na < 8; na++)
                    mma_f16(acc[ma][na], fA1[ma], &fB1[na >> 1][2 * (na & 1)]);

            stg = nstg;
        }
    }

    // ---- epilogue ----
    float* Cfo = (EPI == EPI_NONE) ? (Cf + split * splitStride + (long)bz * sC) : nullptr;
    unsigned short* Ho = (EPI != EPI_NONE) ? reinterpret_cast<unsigned short*>(Ch) : nullptr;
    const int gr = lane >> 2;
    const int gc = (lane & 3) * 2;
#pragma unroll
    for (int ma = 0; ma < 4; ma++) {
#pragma unroll
        for (int half = 0; half < 2; half++) {
            const int row = bm + wm * 64 + ma * 16 + gr + half * 8;
            float rs = 0.f;
#pragma unroll
            for (int na = 0; na < 8; na++) {
                const int col = bn + wn * 64 + na * 8 + gc;
                float v0 = acc[ma][na][half * 2 + 0];
                float v1 = acc[ma][na][half * 2 + 1];
                long off = (long)row * Nd + col;
                if (EPI == EPI_RELUH) {
                    v0 = fmaxf(v0, 0.f); v1 = fmaxf(v1, 0.f);
                    rs += v0 + v1;
                    ushort2 o = make_ushort2(__half_as_ushort(__float2half_rn(v0)),
                                             __half_as_ushort(__float2half_rn(v1)));
                    *reinterpret_cast<ushort2*>(Ho + off) = o;
                } else if (EPI == EPI_RELUMULX) {
                    ushort2 xf = *reinterpret_cast<const ushort2*>(Xf + off);
                    float x0 = __half2float(__ushort_as_half(xf.x));
                    float x1 = __half2float(__ushort_as_half(xf.y));
                    v0 = fmaxf(v0, 0.f) * x0 * (1.f / 16.f);
                    v1 = fmaxf(v1, 0.f) * x1 * (1.f / 16.f);
                    ushort2 o = make_ushort2(__half_as_ushort(__float2half_rn(v0)),
                                             __half_as_ushort(__float2half_rn(v1)));
                    *reinterpret_cast<ushort2*>(Ho + off) = o;
                } else {
                    *reinterpret_cast<float2*>(Cfo + off) = make_float2(v0, v1);
                }
            }
            if (EPI == EPI_RELUH) {
                rs += __shfl_xor_sync(0xffffffffu, rs, 1);
                rs += __shfl_xor_sync(0xffffffffu, rs, 2);
                if ((lane & 3) == 0) atomicAdd(&g_CS[row], rs);
            }
        }
    }
}

// -- Scores kernel: 128x128 tiles, triangular skip, 3-stage, 2 CTA/SM (R11) ----
#define SK_TILE  8192
#define SK_STAGE (2 * SK_TILE)
#define SK_SMEM  (3 * SK_STAGE)      // 49152

__global__ void __launch_bounds__(256, 2) mma_sk(
    const __half* __restrict__ Xh, float* __restrict__ Cf, int kLen)
{
    extern __shared__ char smem[];
    const uint32_t sb = smem_u32(smem);
    const int tid  = threadIdx.x;
    const int lane = tid & 31;
    const int wid  = tid >> 5;
    const int wm   = wid >> 2;
    const int wn   = wid & 3;
    const int zz   = blockIdx.z;
    const int split = zz >> 5;
    const int bz    = zz & 31;
    const long kOff = (long)split * kLen;
    const int bm = blockIdx.y * 128;
    const int bn = blockIdx.x * 128;
    const bool skip = (bn >= bm + 128);

    float acc[4][4][4];
#pragma unroll
    for (int i = 0; i < 4; i++)
#pragma unroll
        for (int j = 0; j < 4; j++)
#pragma unroll
            for (int v = 0; v < 4; v++) acc[i][j][v] = 0.f;

    if (!skip) {
        const __half* Ahp = Xh + (long)bz * T_ * N_ + (long)bm * N_ + kOff;
        const __half* Bhp = Xh + (long)bz * T_ * N_ + (long)bn * N_ + kOff;

        const int qr0 = tid >> 2;
        const int qc0 = tid & 3;
        auto stage_load = [&](int stg, int k0) {
            uint32_t base = sb + stg * SK_STAGE;
#pragma unroll
            for (int i = 0; i < 2; i++) {
                int r = qr0 + i * 64;
                uint32_t so = (uint32_t)(r * 64 + ((qc0 ^ ((r >> 1) & 3)) * 16));
                long gofs = (long)r * N_ + k0 + qc0 * 8;
                cp16(base + so, Ahp + gofs);
                cp16(base + SK_TILE + so, Bhp + gofs);
            }
            cp_commit();
        };

        const int nC = kLen / 32;
        stage_load(0, 0);
        stage_load(1, 32);

        const uint32_t aRow  = (uint32_t)(wm * 64 + (lane & 15));
        const uint32_t aColG = (uint32_t)(lane >> 4);
        const uint32_t bRow  = (uint32_t)(wn * 32 + ((lane >> 4) << 3) + (lane & 7));
        const uint32_t bColG = (uint32_t)((lane >> 3) & 1);
        const uint32_t sa  = (aRow >> 1) & 3;
        const uint32_t sbw = (bRow >> 1) & 3;
        uint32_t aoff[2], boff[2];
#pragma unroll
        for (int ks = 0; ks < 2; ks++) {
            aoff[ks] = aRow * 64 + (((ks * 2 + aColG) ^ sa) * 16);
            boff[ks] = bRow * 64 + (((ks * 2 + bColG) ^ sbw) * 16);
        }

        int stg = 0;
        for (int c = 0; c < nC; c++) {
            cp_wait<1>();
            __syncthreads();
            if (c + 2 < nC) {
                int ns = stg + 2; if (ns >= 3) ns -= 3;
                stage_load(ns, (c + 2) * 32);
            } else {
                cp_commit();
            }

            const uint32_t st = sb + stg * SK_STAGE;
#pragma unroll
            for (int ks = 0; ks < 2; ks++) {
                uint32_t fA[4][4], fB[2][4];
#pragma unroll
                for (int ma = 0; ma < 4; ma++)
                    ldsm_x4(fA[ma], st + aoff[ks] + ma * 1024);
#pragma unroll
                for (int p = 0; p < 2; p++)
                    ldsm_x4(fB[p], st + SK_TILE + boff[ks] + p * 1024);
#pragma unroll
                for (int ma = 0; ma < 4; ma++)
#pragma unroll
                    for (int na = 0; na < 4; na++)
                        mma_f16(acc[ma][na], fA[ma], &fB[na >> 1][2 * (na & 1)]);
            }
            stg = (stg == 2) ? 0 : stg + 1;
        }
    }

    float* Cfo = Cf + (long)split * B_ * T_ * T_ + (long)bz * T_ * T_;
    const int gr = lane >> 2;
    const int gc = (lane & 3) * 2;
#pragma unroll
    for (int ma = 0; ma < 4; ma++) {
#pragma unroll
        for (int half = 0; half < 2; half++) {
            const int row = bm + wm * 64 + ma * 16 + gr + half * 8;
#pragma unroll
            for (int na = 0; na < 4; na++) {
                const int col = bn + wn * 32 + na * 8 + gc;
                *reinterpret_cast<float2*>(Cfo + (long)row * T_ + col) =
                    make_float2(acc[ma][na][half * 2 + 0], acc[ma][na][half * 2 + 1]);
            }
        }
    }
}

// ---------------- SIMT NN GEMM: a* = (decayed S) @ U, split-K x2 ----------------
#define GBM 128
#define GBN 64
#define GBK 16
#define GTM 8
#define GTN 4

__global__ __launch_bounds__(256)
void gemm_nn(const float* __restrict__ A0, const float* __restrict__ A1,
             const float* __restrict__ B, float* __restrict__ C)
{
    const int zz = blockIdx.z;
    const int bz = zz & 31;
    const int split = zz >> 5;
    A0 += (long)bz * T_ * T_;
    A1 += (long)bz * T_ * T_;
    B  += (long)bz * T_ * D_;
    C  += (long)split * M_ * D_ + (long)bz * T_ * D_;
    const int bm = blockIdx.y * GBM;
    const int bn = blockIdx.x * GBN;

    __shared__ __align__(16) float As[GBK][GBM + 4];
    __shared__ __align__(16) float Bs[GBK][GBN + 4];

    const int tid = threadIdx.x;
    const int tx = tid & 15;
    const int ty = tid >> 4;

    float acc[GTM][GTN];
#pragma unroll
    for (int i = 0; i < GTM; i++)
#pragma unroll
        for (int j = 0; j < GTN; j++) acc[i][j] = 0.f;

    const int lr = tid >> 2;
    const int lk = (tid & 3) * 4;
    const int brow = tid >> 4;
    const int bcol = (tid & 15) * 4;

    const int kBeg = split * (T_ / 2);
    for (int k0 = kBeg; k0 < kBeg + T_ / 2; k0 += GBK) {
#pragma unroll
        for (int i = 0; i < 2; i++) {
            int r = lr + i * 64;
            int t = bm + r;
            long ao = (long)t * T_ + k0 + lk;
            float4 v = *reinterpret_cast<const float4*>(A0 + ao);
            float4 w = *reinterpret_cast<const float4*>(A1 + ao);
            float vv[4] = {v.x + w.x, v.y + w.y, v.z + w.z, v.w + w.w};
#pragma unroll
            for (int j = 0; j < 4; j++) {
                int L = t - (k0 + lk + j);
                As[lk + j][r] = (L > 0) ? vv[j] * g_DEC[L] : 0.f;
            }
        }
        {
            float4 v = *reinterpret_cast<const float4*>(B + (long)(k0 + brow) * D_ + bn + bcol);
            Bs[brow][bcol + 0] = v.x; Bs[brow][bcol + 1] = v.y;
            Bs[brow][bcol + 2] = v.z; Bs[brow][bcol + 3] = v.w;
        }
        __syncthreads();
#pragma unroll
        for (int kk = 0; kk < GBK; kk++) {
            float af[GTM], bf[GTN];
#pragma unroll
            for (int i = 0; i < GTM; i++) af[i] = As[kk][ty * GTM + i];
#pragma unroll
            for (int j = 0; j < GTN; j++) bf[j] = Bs[kk][tx * GTN + j];
#pragma unroll
            for (int i = 0; i < GTM; i++)
#pragma unroll
                for (int j = 0; j < GTN; j++)
                    acc[i][j] = fmaf(af[i], bf[j], acc[i][j]);
        }
        __syncthreads();
    }
#pragma unroll
    for (int i = 0; i < GTM; i++) {
        int row = bm + ty * GTM + i;
        long cbase = (long)row * D_ + bn + tx * GTN;
        *reinterpret_cast<float4*>(C + cbase) = make_float4(acc[i][0], acc[i][1], acc[i][2], acc[i][3]);
    }
}

// ---------------- elementwise / scan / LN kernels ----------------
__device__ __forceinline__ float blockReduceSum256(float v) {
    __shared__ float sh[8];
    __syncthreads();
    int lane = threadIdx.x & 31;
    int w = threadIdx.x >> 5;
#pragma unroll
    for (int o = 16; o > 0; o >>= 1) v += __shfl_down_sync(0xffffffffu, v, o);
    if (lane == 0) sh[w] = v;
    __syncthreads();
    if (w == 0) {
        float t = (lane < 8) ? sh[lane] : 0.f;
#pragma unroll
        for (int o = 4; o > 0; o >>= 1) t += __shfl_down_sync(0xffffffffu, t, o);
        if (lane == 0) sh[0] = t;
    }
    __syncthreads();
    return sh[0];
}

// fused: Dx x16, Dy x64, E x64 -> fp16; emb gather x16 -> fp16; g_CS zero; g_DEC
__global__ void conv_gather_kernel(const float* __restrict__ Dx, const float* __restrict__ Dy,
                                   const float* __restrict__ E, const float* __restrict__ emb,
                                   const int* __restrict__ idx)
{
    int blk = blockIdx.x;
    if (blk < 3072) {
        const float* src;
        __half* hi;
        float scale;
        int local;
        if (blk < 1024)      { src = Dx; hi = g_DxH; scale = 16.f; local = blk; }
        else if (blk < 2048) { src = Dy; hi = g_DyH; scale = 64.f; local = blk - 1024; }
        else                 { src = E;  hi = g_EH;  scale = 64.f; local = blk - 2048; }
        long i = (long)local * 256 + threadIdx.x;
        float4 v = reinterpret_cast<const float4*>(src)[i];
        ushort4 o = make_ushort4(
            __half_as_ushort(__float2half_rn(v.x * scale)),
            __half_as_ushort(__float2half_rn(v.y * scale)),
            __half_as_ushort(__float2half_rn(v.z * scale)),
            __half_as_ushort(__float2half_rn(v.w * scale)));
        reinterpret_cast<ushort4*>(hi)[i] = o;
        if (blk == 0 && threadIdx.x == 0) {
            float d = 1.f;
            for (int t = 0; t < T_; t++) { g_DEC[t] = d * (1.f / 65536.f); d *= DECF; }
        }
    } else {
        int m = (blk - 3072) * 4 + (threadIdx.x >> 6);
        int t = threadIdx.x & 63;
        if (t == 0) g_CS[m] = 0.f;
        float4 v = *reinterpret_cast<const float4*>(emb + (long)idx[m] * D_ + t * 4);
        ushort4 o = make_ushort4(
            __half_as_ushort(__float2half_rn(v.x * 16.f)),
            __half_as_ushort(__float2half_rn(v.y * 16.f)),
            __half_as_ushort(__float2half_rn(v.z * 16.f)),
            __half_as_ushort(__float2half_rn(v.w * 16.f)));
        reinterpret_cast<ushort4*>(g_Vf)[(long)m * (D_ / 4) + t] = o;
    }
}

__global__ void screc_kernel() {
    __shared__ float cs[B_ * T_];
    for (int i = threadIdx.x; i < B_ * T_; i += 256) {
        int t = i >> 5, b = i & 31;
        cs[t * 32 + b] = g_CS[b * T_ + t] * (1.f / 256.f);
    }
    __syncthreads();
    if (threadIdx.x < B_) {
        int b = threadIdx.x;
        float sprev = 0.f;
        for (int t = 0; t < T_; t++) {
            float sumx = __fdividef(sprev, sprev + EPSF);
            float s = DECF * sumx + cs[t * 32 + b];
            g_Cc[b * T_ + t] = __fdividef(1.f, s + EPSF);
            sprev = s;
        }
    }
}

// scan on 256-scaled values: X = 256*x (unroll exposes MLP on the P stream)
__global__ void xrecur_kernel() {
    int b = blockIdx.y;
    int n = blockIdx.x * 256 + threadIdx.x;
    __shared__ float sc[T_];
    sc[threadIdx.x] = g_Cc[b * T_ + threadIdx.x];
    __syncthreads();
    float X = 0.f;
    long base = (long)b * T_ * N_ + n;
#pragma unroll 4
    for (int t = 0; t < T_; t++) {
        float p = __half2float(g_Yf[base + (long)t * N_]);
        X = (DECF * X + p) * sc[t];
        g_Xf[base + (long)t * N_] = __float2half_rn(X);
    }
}

// OUT: 0 = fp32, 1 = fp16 single
template <int OUT, int NPART>
__global__ void ln_rows(const float* __restrict__ in, float* __restrict__ outf,
                        unsigned short* __restrict__ oh,
                        const int* __restrict__ gidx, float inscale)
{
    int m = blockIdx.x;
    long r = gidx ? (long)gidx[m] : (long)m;
    float z = in[r * D_ + threadIdx.x];
#pragma unroll
    for (int p = 1; p < NPART; p++)
        z += in[(long)p * M_ * D_ + r * D_ + threadIdx.x];
    z *= inscale;
    float mean = blockReduceSum256(z) * (1.f / D_);
    float d = z - mean;
    float var = blockReduceSum256(d * d) * (1.f / (D_ - 1));
    float v = d / (sqrtf(var) + EPSF);
    long o = (long)m * D_ + threadIdx.x;
    if (OUT == 1) {
        oh[o] = __half_as_ushort(__float2half_rn(v));
    } else {
        outf[o] = v;
    }
}

// ---------------- launch ----------------
extern "C" void kernel_launch(void* const* d_in, const int* in_sizes, int n_in,
                              void* d_out, int out_size)
{
    (void)in_sizes; (void)n_in; (void)out_size;
    const int*   idx  = (const int*)d_in[0];
    const float* temb = (const float*)d_in[1];
    const float* E    = (const float*)d_in[2];
    const float* Dx   = (const float*)d_in[3];
    const float* Dy   = (const float*)d_in[4];
    float* out = (float*)d_out;

    float *pU, *pS, *pA, *pO;
    __half *pVf, *pDxH, *pDyH, *pEH, *pAf, *pXf, *pYf;
    cudaGetSymbolAddress((void**)&pU,  g_U);
    cudaGetSymbolAddress((void**)&pS,  g_S);
    cudaGetSymbolAddress((void**)&pA,  g_A);
    cudaGetSymbolAddress((void**)&pO,  g_O);
    cudaGetSymbolAddress((void**)&pVf, g_Vf);
    cudaGetSymbolAddress((void**)&pDxH, g_DxH);
    cudaGetSymbolAddress((void**)&pDyH, g_DyH);
    cudaGetSymbolAddress((void**)&pEH, g_EH);
    cudaGetSymbolAddress((void**)&pAf, g_Af);
    cudaGetSymbolAddress((void**)&pXf, g_Xf);
    cudaGetSymbolAddress((void**)&pYf, g_Yf);

    cudaFuncSetAttribute(mma_nt<EPI_RELUH>,
                         cudaFuncAttributeMaxDynamicSharedMemorySize, SMEM_SZ);
    cudaFuncSetAttribute(mma_nt<EPI_NONE>,
                         cudaFuncAttributeMaxDynamicSharedMemorySize, SMEM_SZ);
    cudaFuncSetAttribute(mma_nt<EPI_RELUMULX>,
                         cudaFuncAttributeMaxDynamicSharedMemorySize, SMEM_SZ);
    cudaFuncSetAttribute(mma_sk,
                         cudaFuncAttributeMaxDynamicSharedMemorySize, SK_SMEM);

    // fused conversions + gather (+g_DEC, +g_CS zero)
    conv_gather_kernel<<<3072 + M_ / 4, 256>>>(Dx, Dy, E, temb, idx);
    // U = LN(emb[idx])
    ln_rows<0, 1><<<M_, 256>>>(temb, pU, nullptr, idx, 1.f);

    // G1 (fp16): 256*P = relu((16v) @ (16Dx)^T) -> g_Yf (fp16), row-sum -> g_CS
    mma_nt<EPI_RELUH><<<dim3(N_ / 256, M_ / 128, 1), 256, SMEM_SZ>>>(
        pVf, pDxH, nullptr, pYf, nullptr,
        N_, D_, D_, 0, 0, 0, 0, 1);

    // scalar L1 recurrence + parallel x scan; emits 256*x fp16
    screc_kernel<<<1, 256>>>();
    xrecur_kernel<<<dim3(N_ / 256, B_, 1), 256>>>();

    // scores (65536*raw, split-K x2, triangular skip, fp16)
    mma_sk<<<dim3(T_ / 128, T_ / 128, 2 * B_), 256, SK_SMEM>>>(pXf, pS, N_ / 2);

    // a* = (decayed (S0+S1)/65536) @ U  (SIMT fp32, split-K x2; decay+mask+unscale fused)
    gemm_nn<<<dim3(D_ / GBN, T_ / GBM, 2 * B_), 256>>>(
        pS, pS + (long)B_ * T_ * T_, pU, pA);

    // a* <- LN(sum of 2 partials) -> fp16 single
    ln_rows<1, 2><<<M_, 256>>>(pA, nullptr, (unsigned short*)pAf, nullptr, 1.f);

    // G2 (fp16): 1024y = relu(LN(a*) @ (64Dy)^T) * (256x) / 16 -> g_Yf
    mma_nt<EPI_RELUMULX><<<dim3(N_ / 256, M_ / 128, 1), 256, SMEM_SZ>>>(
        pAf, pDyH, nullptr, pYf, pXf,
        N_, D_, D_, 0, 0, 0, 0, 1);

    // G3 (fp16, split-K x2): o_p = (1024y) @ (64E)^T -> g_O partials (65536*o)
    mma_nt<EPI_NONE><<<dim3(D_ / 256, M_ / 128, 2), 256, SMEM_SZ>>>(
        pYf, pEH, pO, nullptr, nullptr,
        D_, N_, N_ / 2, 0, 0, 0, (long)M_ * D_, 1);

    // out = LN((sum of 2 partials) / 65536)
    ln_rows<0, 2><<<M_, 256>>>(pO, out, nullptr, nullptr, 1.f / 65536.f);
}

// round 15
// speedup vs baseline: 1.0879x; 1.0879x over previous
#include <cuda_runtime.h>
#include <cuda_fp16.h>
#include <cstdint>

#define B_   32
#define T_   256
#define N_   4096
#define D_   256
#define M_   (B_ * T_)
#define EPSF 1e-6f
#define DECF 0.97f

// ---------------- scratch (device globals; no allocation) ----------------
__device__ float g_CS[M_];
__device__ float g_Cc[M_];
__device__ float g_S [2LL * B_ * T_ * T_];      // 2 split-K partials of 65536*scores
__device__ float g_A [M_ * D_];                 // 256*a*
__device__ float g_O [2LL * M_ * D_];           // 2 split-K partials of G3
__device__ float g_DEC[T_];                     // 0.97^L / 256 (decay_conv)

// fp16 operands; scalings: v,Dx x16; Dy,E x64; P,x x256; y x1024; S' = 256*raw*dec
__device__ __half g_Vf [M_ * D_];                             // 16*emb[idx]
__device__ __half g_DxH[N_ * D_];                             // 16*Dx
__device__ __half g_DyH[N_ * D_];                             // 64*Dy
__device__ __half g_EH [D_ * N_];                             // 64*E
__device__ __half g_Uh [M_ * D_];                             // LN(v) fp16 [b,s][d]
__device__ __half g_UT [M_ * D_];                             // transposed [b][d][s]
__device__ __half g_Sf [(long long)B_ * T_ * T_];             // decayed fp16 scores
__device__ __half g_Af [M_ * D_];                             // LN(a*) fp16
__device__ __half g_Xf [(long long)M_ * N_];                  // 256*x fp16
__device__ __half g_Yf [(long long)M_ * N_];                  // 256*P, then 1024*y fp16

// ---------------- PTX helpers (baseline ISA only) ----------------
__device__ __forceinline__ uint32_t smem_u32(const void* p) {
    uint32_t a;
    asm("{ .reg .u64 t; cvta.to.shared.u64 t, %1; cvt.u32.u64 %0, t; }" : "=r"(a) : "l"(p));
    return a;
}
__device__ __forceinline__ void cp16(uint32_t so, const void* g) {
    asm volatile("cp.async.cg.shared.global [%0], [%1], 16;" :: "r"(so), "l"(g));
}
__device__ __forceinline__ void cp_commit() {
    asm volatile("cp.async.commit_group;" ::: "memory");
}
template <int NN>
__device__ __forceinline__ void cp_wait() {
    asm volatile("cp.async.wait_group %0;" :: "n"(NN) : "memory");
}
__device__ __forceinline__ void ldsm_x4(uint32_t* f, uint32_t a) {
    asm volatile("ldmatrix.sync.aligned.m8n8.x4.shared.b16 {%0,%1,%2,%3}, [%4];"
        : "=r"(f[0]), "=r"(f[1]), "=r"(f[2]), "=r"(f[3]) : "r"(a));
}
__device__ __forceinline__ void mma_f16(float* c, const uint32_t* a, const uint32_t* b) {
    asm volatile("mma.sync.aligned.m16n8k16.row.col.f32.f16.f16.f32 "
        "{%0,%1,%2,%3}, {%4,%5,%6,%7}, {%8,%9}, {%0,%1,%2,%3};"
        : "+f"(c[0]), "+f"(c[1]), "+f"(c[2]), "+f"(c[3])
        : "r"(a[0]), "r"(a[1]), "r"(a[2]), "r"(a[3]), "r"(b[0]), "r"(b[1]));
}

// -- Main HMMA NT GEMM: CTA 128x256, warp 64x64, cross-chunk fragment pipelining
enum { EPI_NONE = 0, EPI_RELUH = 1, EPI_RELUMULX = 2 };

#define TILE_A  8192
#define TILE_BT 16384
#define STAGE_B (TILE_A + TILE_BT)
#define NSTG    4
#define SMEM_SZ (NSTG * STAGE_B)     // 98304

template <int EPI>
__global__ void __launch_bounds__(256, 1) mma_nt(
    const __half* __restrict__ Ah, const __half* __restrict__ Bh,
    float* __restrict__ Cf, __half* __restrict__ Ch,
    const __half* __restrict__ Xf,
    int Nd, int K, int kLen, long sA, long sB, long sC, long splitStride, int batches)
{
    extern __shared__ char smem[];
    const uint32_t sb = smem_u32(smem);
    const int tid  = threadIdx.x;
    const int lane = tid & 31;
    const int wid  = tid >> 5;
    const int wm   = wid >> 2;
    const int wn   = wid & 3;
    const int zz   = blockIdx.z;
    const int split = zz / batches;
    const int bz    = zz - split * batches;
    const long kOff = (long)split * kLen;
    const int bm = blockIdx.y * 128;
    const int bn = blockIdx.x * 256;

    float acc[4][8][4];
#pragma unroll
    for (int i = 0; i < 4; i++)
#pragma unroll
        for (int j = 0; j < 8; j++)
#pragma unroll
            for (int v = 0; v < 4; v++) acc[i][j][v] = 0.f;

    {
        const __half* Ahp = Ah + (long)bz * sA + (long)bm * K + kOff;
        const __half* Bhp = Bh + (long)bz * sB + (long)bn * K + kOff;

        const int qr0 = tid >> 2;
        const int qc0 = tid & 3;
        auto stage_load = [&](int stg, int k0) {
            uint32_t base = sb + stg * STAGE_B;
#pragma unroll
            for (int i = 0; i < 2; i++) {
                int r = qr0 + i * 64;
                uint32_t so = (uint32_t)(r * 64 + ((qc0 ^ ((r >> 1) & 3)) * 16));
                cp16(base + so, Ahp + (long)r * K + k0 + qc0 * 8);
            }
#pragma unroll
            for (int i = 0; i < 4; i++) {
                int r = qr0 + i * 64;
                uint32_t so = (uint32_t)(r * 64 + ((qc0 ^ ((r >> 1) & 3)) * 16));
                cp16(base + TILE_A + so, Bhp + (long)r * K + k0 + qc0 * 8);
            }
            cp_commit();
        };

        const int nC = kLen / 32;
        stage_load(0, 0);
        stage_load(1, 32);
        stage_load(2, 64);

        const uint32_t aRow  = (uint32_t)(wm * 64 + (lane & 15));
        const uint32_t aColG = (uint32_t)(lane >> 4);
        const uint32_t bRow  = (uint32_t)(wn * 64 + ((lane >> 4) << 3) + (lane & 7));
        const uint32_t bColG = (uint32_t)((lane >> 3) & 1);
        const uint32_t sa  = (aRow >> 1) & 3;
        const uint32_t sbw = (bRow >> 1) & 3;
        uint32_t aoff[2], boff[2];
#pragma unroll
        for (int ks = 0; ks < 2; ks++) {
            aoff[ks] = aRow * 64 + (((ks * 2 + aColG) ^ sa) * 16);
            boff[ks] = bRow * 64 + (((ks * 2 + bColG) ^ sbw) * 16);
        }

        uint32_t fA0[4][4], fB0[4][4], fA1[4][4], fB1[4][4];

        cp_wait<2>();
        __syncthreads();
#pragma unroll
        for (int ma = 0; ma < 4; ma++)
            ldsm_x4(fA0[ma], sb + aoff[0] + ma * 1024);
#pragma unroll
        for (int p = 0; p < 4; p++)
            ldsm_x4(fB0[p], sb + TILE_A + boff[0] + p * 1024);

        int stg = 0;
        for (int c = 0; c < nC; c++) {
            __syncthreads();
            if (c + 3 < nC) {
                int ns = stg + 3; if (ns >= NSTG) ns -= NSTG;
                stage_load(ns, (c + 3) * 32);
            } else {
                cp_commit();
            }

            const uint32_t st = sb + stg * STAGE_B;
#pragma unroll
            for (int ma = 0; ma < 4; ma++)
                ldsm_x4(fA1[ma], st + aoff[1] + ma * 1024);
#pragma unroll
            for (int p = 0; p < 4; p++)
                ldsm_x4(fB1[p], st + TILE_A + boff[1] + p * 1024);
#pragma unroll
            for (int ma = 0; ma < 4; ma++)
#pragma unroll
                for (int na = 0; na < 8; na++)
                    mma_f16(acc[ma][na], fA0[ma], &fB0[na >> 1][2 * (na & 1)]);

            cp_wait<2>();
            int nstg = stg + 1; if (nstg >= NSTG) nstg = 0;
            if (c + 1 < nC) {
                const uint32_t st2 = sb + nstg * STAGE_B;
#pragma unroll
                for (int ma = 0; ma < 4; ma++)
                    ldsm_x4(fA0[ma], st2 + aoff[0] + ma * 1024);
#pragma unroll
                for (int p = 0; p < 4; p++)
                    ldsm_x4(fB0[p], st2 + TILE_A + boff[0] + p * 1024);
            }
#pragma unroll
            for (int ma = 0; ma < 4; ma++)
#pragma unroll
                for (int na = 0; na < 8; na++)
                    mma_f16(acc[ma][na], fA1[ma], &fB1[na >> 1][2 * (na & 1)]);

            stg = nstg;
        }
    }

    float* Cfo = (EPI == EPI_NONE) ? (Cf + split * splitStride + (long)bz * sC) : nullptr;
    unsigned short* Ho = (EPI != EPI_NONE) ? reinterpret_cast<unsigned short*>(Ch) : nullptr;
    const int gr = lane >> 2;
    const int gc = (lane & 3) * 2;
#pragma unroll
    for (int ma = 0; ma < 4; ma++) {
#pragma unroll
        for (int half = 0; half < 2; half++) {
            const int row = bm + wm * 64 + ma * 16 + gr + half * 8;
            float rs = 0.f;
#pragma unroll
            for (int na = 0; na < 8; na++) {
                const int col = bn + wn * 64 + na * 8 + gc;
                float v0 = acc[ma][na][half * 2 + 0];
                float v1 = acc[ma][na][half * 2 + 1];
                long off = (long)row * Nd + col;
                if (EPI == EPI_RELUH) {
                    v0 = fmaxf(v0, 0.f); v1 = fmaxf(v1, 0.f);
                    rs += v0 + v1;
                    ushort2 o = make_ushort2(__half_as_ushort(__float2half_rn(v0)),
                                             __half_as_ushort(__float2half_rn(v1)));
                    *reinterpret_cast<ushort2*>(Ho + off) = o;
                } else if (EPI == EPI_RELUMULX) {
                    ushort2 xf = *reinterpret_cast<const ushort2*>(Xf + off);
                    float x0 = __half2float(__ushort_as_half(xf.x));
                    float x1 = __half2float(__ushort_as_half(xf.y));
                    v0 = fmaxf(v0, 0.f) * x0 * (1.f / 16.f);
                    v1 = fmaxf(v1, 0.f) * x1 * (1.f / 16.f);
                    ushort2 o = make_ushort2(__half_as_ushort(__float2half_rn(v0)),
                                             __half_as_ushort(__float2half_rn(v1)));
                    *reinterpret_cast<ushort2*>(Ho + off) = o;
                } else {
                    *reinterpret_cast<float2*>(Cfo + off) = make_float2(v0, v1);
                }
            }
            if (EPI == EPI_RELUH) {
                rs += __shfl_xor_sync(0xffffffffu, rs, 1);
                rs += __shfl_xor_sync(0xffffffffu, rs, 2);
                if ((lane & 3) == 0) atomicAdd(&g_CS[row], rs);
            }
        }
    }
}

// -- a* HMMA: 128x128 tiles, 3-stage, 2 CTA/SM; A=S'(fp16), B=UT(fp16), C=fp32 --
#define AK_TILE  8192
#define AK_STAGE (2 * AK_TILE)
#define AK_SMEM  (3 * AK_STAGE)      // 49152

__global__ void __launch_bounds__(256, 2) mma_a(
    const __half* __restrict__ Sa, const __half* __restrict__ Ut,
    float* __restrict__ Cf)
{
    extern __shared__ char smem[];
    const uint32_t sb = smem_u32(smem);
    const int tid  = threadIdx.x;
    const int lane = tid & 31;
    const int wid  = tid >> 5;
    const int wm   = wid >> 2;
    const int wn   = wid & 3;
    const int bz = blockIdx.z;
    const int bm = blockIdx.y * 128;
    const int bn = blockIdx.x * 128;

    float acc[4][4][4];
#pragma unroll
    for (int i = 0; i < 4; i++)
#pragma unroll
        for (int j = 0; j < 4; j++)
#pragma unroll
            for (int v = 0; v < 4; v++) acc[i][j][v] = 0.f;

    {
        const __half* Ahp = Sa + (long)bz * T_ * T_ + (long)bm * T_;
        const __half* Bhp = Ut + (long)bz * D_ * T_ + (long)bn * T_;

        const int qr0 = tid >> 2;
        const int qc0 = tid & 3;
        auto stage_load = [&](int stg, int k0) {
            uint32_t base = sb + stg * AK_STAGE;
#pragma unroll
            for (int i = 0; i < 2; i++) {
                int r = qr0 + i * 64;
                uint32_t so = (uint32_t)(r * 64 + ((qc0 ^ ((r >> 1) & 3)) * 16));
                long gofs = (long)r * T_ + k0 + qc0 * 8;
                cp16(base + so, Ahp + gofs);
                cp16(base + AK_TILE + so, Bhp + gofs);
            }
            cp_commit();
        };

        const int nC = T_ / 32;
        stage_load(0, 0);
        stage_load(1, 32);

        const uint32_t aRow  = (uint32_t)(wm * 64 + (lane & 15));
        const uint32_t aColG = (uint32_t)(lane >> 4);
        const uint32_t bRow  = (uint32_t)(wn * 32 + ((lane >> 4) << 3) + (lane & 7));
        const uint32_t bColG = (uint32_t)((lane >> 3) & 1);
        const uint32_t sa  = (aRow >> 1) & 3;
        const uint32_t sbw = (bRow >> 1) & 3;
        uint32_t aoff[2], boff[2];
#pragma unroll
        for (int ks = 0; ks < 2; ks++) {
            aoff[ks] = aRow * 64 + (((ks * 2 + aColG) ^ sa) * 16);
            boff[ks] = bRow * 64 + (((ks * 2 + bColG) ^ sbw) * 16);
        }

        int stg = 0;
        for (int c = 0; c < nC; c++) {
            cp_wait<1>();
            __syncthreads();
            if (c + 2 < nC) {
                int ns = stg + 2; if (ns >= 3) ns -= 3;
                stage_load(ns, (c + 2) * 32);
            } else {
                cp_commit();
            }

            const uint32_t st = sb + stg * AK_STAGE;
#pragma unroll
            for (int ks = 0; ks < 2; ks++) {
                uint32_t fA[4][4], fB[2][4];
#pragma unroll
                for (int ma = 0; ma < 4; ma++)
                    ldsm_x4(fA[ma], st + aoff[ks] + ma * 1024);
#pragma unroll
                for (int p = 0; p < 2; p++)
                    ldsm_x4(fB[p], st + AK_TILE + boff[ks] + p * 1024);
#pragma unroll
                for (int ma = 0; ma < 4; ma++)
#pragma unroll
                    for (int na = 0; na < 4; na++)
                        mma_f16(acc[ma][na], fA[ma], &fB[na >> 1][2 * (na & 1)]);
            }
            stg = (stg == 2) ? 0 : stg + 1;
        }
    }

    float* Cfo = Cf + (long)bz * T_ * D_;
    const int gr = lane >> 2;
    const int gc = (lane & 3) * 2;
#pragma unroll
    for (int ma = 0; ma < 4; ma++) {
#pragma unroll
        for (int half = 0; half < 2; half++) {
            const int row = bm + wm * 64 + ma * 16 + gr + half * 8;
#pragma unroll
            for (int na = 0; na < 4; na++) {
                const int col = bn + wn * 32 + na * 8 + gc;
                *reinterpret_cast<float2*>(Cfo + (long)row * D_ + col) =
                    make_float2(acc[ma][na][half * 2 + 0], acc[ma][na][half * 2 + 1]);
            }
        }
    }
}

// ---------------- elementwise / scan / LN kernels ----------------
__device__ __forceinline__ float blockReduceSum256(float v) {
    __shared__ float sh[8];
    __syncthreads();
    int lane = threadIdx.x & 31;
    int w = threadIdx.x >> 5;
#pragma unroll
    for (int o = 16; o > 0; o >>= 1) v += __shfl_down_sync(0xffffffffu, v, o);
    if (lane == 0) sh[w] = v;
    __syncthreads();
    if (w == 0) {
        float t = (lane < 8) ? sh[lane] : 0.f;
#pragma unroll
        for (int o = 4; o > 0; o >>= 1) t += __shfl_down_sync(0xffffffffu, t, o);
        if (lane == 0) sh[0] = t;
    }
    __syncthreads();
    return sh[0];
}

__global__ void conv_gather_kernel(const float* __restrict__ Dx, const float* __restrict__ Dy,
                                   const float* __restrict__ E, const float* __restrict__ emb,
                                   const int* __restrict__ idx)
{
    int blk = blockIdx.x;
    if (blk < 3072) {
        const float* src;
        __half* hi;
        float scale;
        int local;
        if (blk < 1024)      { src = Dx; hi = g_DxH; scale = 16.f; local = blk; }
        else if (blk < 2048) { src = Dy; hi = g_DyH; scale = 64.f; local = blk - 1024; }
        else                 { src = E;  hi = g_EH;  scale = 64.f; local = blk - 2048; }
        long i = (long)local * 256 + threadIdx.x;
        float4 v = reinterpret_cast<const float4*>(src)[i];
        ushort4 o = make_ushort4(
            __half_as_ushort(__float2half_rn(v.x * scale)),
            __half_as_ushort(__float2half_rn(v.y * scale)),
            __half_as_ushort(__float2half_rn(v.z * scale)),
            __half_as_ushort(__float2half_rn(v.w * scale)));
        reinterpret_cast<ushort4*>(hi)[i] = o;
        if (blk == 0 && threadIdx.x == 0) {
            float d = 1.f;
            for (int t = 0; t < T_; t++) { g_DEC[t] = d * (1.f / 256.f); d *= DECF; }
        }
    } else {
        int m = (blk - 3072) * 4 + (threadIdx.x >> 6);
        int t = threadIdx.x & 63;
        if (t == 0) g_CS[m] = 0.f;
        float4 v = *reinterpret_cast<const float4*>(emb + (long)idx[m] * D_ + t * 4);
        ushort4 o = make_ushort4(
            __half_as_ushort(__float2half_rn(v.x * 16.f)),
            __half_as_ushort(__float2half_rn(v.y * 16.f)),
            __half_as_ushort(__float2half_rn(v.z * 16.f)),
            __half_as_ushort(__float2half_rn(v.w * 16.f)));
        reinterpret_cast<ushort4*>(g_Vf)[(long)m * (D_ / 4) + t] = o;
    }
}

__global__ void screc_kernel() {
    __shared__ float cs[B_ * T_];
    for (int i = threadIdx.x; i < B_ * T_; i += 256) {
        int t = i >> 5, b = i & 31;
        cs[t * 32 + b] = g_CS[b * T_ + t] * (1.f / 256.f);
    }
    __syncthreads();
    if (threadIdx.x < B_) {
        int b = threadIdx.x;
        float sprev = 0.f;
        for (int t = 0; t < T_; t++) {
            float sumx = __fdividef(sprev, sprev + EPSF);
            float s = DECF * sumx + cs[t * 32 + b];
            g_Cc[b * T_ + t] = __fdividef(1.f, s + EPSF);
            sprev = s;
        }
    }
}

__global__ void xrecur_kernel() {
    int b = blockIdx.y;
    int n = blockIdx.x * 256 + threadIdx.x;
    __shared__ float sc[T_];
    sc[threadIdx.x] = g_Cc[b * T_ + threadIdx.x];
    __syncthreads();
    float X = 0.f;
    long base = (long)b * T_ * N_ + n;
#pragma unroll 4
    for (int t = 0; t < T_; t++) {
        float p = __half2float(g_Yf[base + (long)t * N_]);
        X = (DECF * X + p) * sc[t];
        g_Xf[base + (long)t * N_] = __float2half_rn(X);
    }
}

__global__ void decay_conv_kernel(const float* __restrict__ S0, const float* __restrict__ S1,
                                  __half* __restrict__ Sf)
{
    int m = blockIdx.x;
    int t = m & (T_ - 1);
    int s0 = threadIdx.x * 4;
    long o = (long)m * T_ + s0;
    float4 a = *reinterpret_cast<const float4*>(S0 + o);
    float4 b = *reinterpret_cast<const float4*>(S1 + o);
    float vv[4] = {a.x + b.x, a.y + b.y, a.z + b.z, a.w + b.w};
    unsigned short os[4];
#pragma unroll
    for (int j = 0; j < 4; j++) {
        int L = t - (s0 + j);
        float v = (L > 0) ? vv[j] * g_DEC[L] : 0.f;
        os[j] = __half_as_ushort(__float2half_rn(v));
    }
    *reinterpret_cast<ushort4*>(reinterpret_cast<unsigned short*>(Sf) + o) =
        make_ushort4(os[0], os[1], os[2], os[3]);
}

__global__ void transU_kernel() {
    __shared__ unsigned short tl[32][33];
    int b = blockIdx.z;
    int s0 = blockIdx.x * 32, d0 = blockIdx.y * 32;
    const unsigned short* src = reinterpret_cast<const unsigned short*>(g_Uh);
    unsigned short* dst = reinterpret_cast<unsigned short*>(g_UT);
#pragma unroll
    for (int i = threadIdx.y; i < 32; i += 8)
        tl[i][threadIdx.x] = src[((long)b * T_ + s0 + i) * D_ + d0 + threadIdx.x];
    __syncthreads();
#pragma unroll
    for (int i = threadIdx.y; i < 32; i += 8)
        dst[(long)b * D_ * T_ + (long)(d0 + i) * T_ + s0 + threadIdx.x] = tl[threadIdx.x][i];
}

template <int OUT, int NPART>
__global__ void ln_rows(const float* __restrict__ in, float* __restrict__ outf,
                        unsigned short* __restrict__ oh,
                        const int* __restrict__ gidx, float inscale)
{
    int m = blockIdx.x;
    long r = gidx ? (long)gidx[m] : (long)m;
    float z = in[r * D_ + threadIdx.x];
#pragma unroll
    for (int p = 1; p < NPART; p++)
        z += in[(long)p * M_ * D_ + r * D_ + threadIdx.x];
    z *= inscale;
    float mean = blockReduceSum256(z) * (1.f / D_);
    float d = z - mean;
    float var = blockReduceSum256(d * d) * (1.f / (D_ - 1));
    float v = d / (sqrtf(var) + EPSF);
    long o = (long)m * D_ + threadIdx.x;
    if (OUT == 1) {
        oh[o] = __half_as_ushort(__float2half_rn(v));
    } else {
        outf[o] = v;
    }
}

// ---------------- launch ----------------
extern "C" void kernel_launch(void* const* d_in, const int* in_sizes, int n_in,
                              void* d_out, int out_size)
{
    (void)in_sizes; (void)n_in; (void)out_size;
    const int*   idx  = (const int*)d_in[0];
    const float* temb = (const float*)d_in[1];
    const float* E    = (const float*)d_in[2];
    const float* Dx   = (const float*)d_in[3];
    const float* Dy   = (const float*)d_in[4];
    float* out = (float*)d_out;

    float *pS, *pA, *pO;
    __half *pVf, *pDxH, *pDyH, *pEH, *pUh, *pUT, *pSf, *pAf, *pXf, *pYf;
    cudaGetSymbolAddress((void**)&pS,  g_S);
    cudaGetSymbolAddress((void**)&pA,  g_A);
    cudaGetSymbolAddress((void**)&pO,  g_O);
    cudaGetSymbolAddress((void**)&pVf, g_Vf);
    cudaGetSymbolAddress((void**)&pDxH, g_DxH);
    cudaGetSymbolAddress((void**)&pDyH, g_DyH);
    cudaGetSymbolAddress((void**)&pEH, g_EH);
    cudaGetSymbolAddress((void**)&pUh, g_Uh);
    cudaGetSymbolAddress((void**)&pUT, g_UT);
    cudaGetSymbolAddress((void**)&pSf, g_Sf);
    cudaGetSymbolAddress((void**)&pAf, g_Af);
    cudaGetSymbolAddress((void**)&pXf, g_Xf);
    cudaGetSymbolAddress((void**)&pYf, g_Yf);

    cudaFuncSetAttribute(mma_nt<EPI_RELUH>,
                         cudaFuncAttributeMaxDynamicSharedMemorySize, SMEM_SZ);
    cudaFuncSetAttribute(mma_nt<EPI_NONE>,
                         cudaFuncAttributeMaxDynamicSharedMemorySize, SMEM_SZ);
    cudaFuncSetAttribute(mma_nt<EPI_RELUMULX>,
                         cudaFuncAttributeMaxDynamicSharedMemorySize, SMEM_SZ);
    cudaFuncSetAttribute(mma_a,
                         cudaFuncAttributeMaxDynamicSharedMemorySize, AK_SMEM);

    conv_gather_kernel<<<3072 + M_ / 4, 256>>>(Dx, Dy, E, temb, idx);
    // U = LN(emb[idx]) -> fp16, then transpose to [b][d][s]
    ln_rows<1, 1><<<M_, 256>>>(temb, nullptr, (unsigned short*)pUh, idx, 1.f);
    transU_kernel<<<dim3(8, 8, B_), dim3(32, 8)>>>();

    // G1 (fp16): 256*P = relu((16v) @ (16Dx)^T) -> g_Yf, row-sum -> g_CS
    mma_nt<EPI_RELUH><<<dim3(N_ / 256, M_ / 128, 1), 256, SMEM_SZ>>>(
        pVf, pDxH, nullptr, pYf, nullptr,
        N_, D_, D_, 0, 0, 0, 0, 1);

    screc_kernel<<<1, 256>>>();
    xrecur_kernel<<<dim3(N_ / 256, B_, 1), 256>>>();

    // scores (65536*raw, split-K x2, 256-wide pipelined kernel)
    mma_nt<EPI_NONE><<<dim3(T_ / 256, T_ / 128, 2 * B_), 256, SMEM_SZ>>>(
        pXf, pXf, pS, nullptr, nullptr,
        T_, N_, N_ / 2, (long)T_ * N_, (long)T_ * N_, (long)T_ * T_,
        (long)B_ * T_ * T_, B_);

    // decay+mask -> fp16 S' = 256*raw*dec
    decay_conv_kernel<<<M_, 64>>>(pS, pS + (long)B_ * T_ * T_, pSf);

    // 256*a* = S' @ UT (HMMA)
    mma_a<<<dim3(D_ / 128, T_ / 128, B_), 256, AK_SMEM>>>(pSf, pUT, pA);

    // a* <- LN(a*) with exact 1/256 unscale -> fp16
    ln_rows<1, 1><<<M_, 256>>>(pA, nullptr, (unsigned short*)pAf, nullptr, 1.f / 256.f);

    // G2 (fp16): 1024y = relu(LN(a*) @ (64Dy)^T) * (256x) / 16 -> g_Yf
    mma_nt<EPI_RELUMULX><<<dim3(N_ / 256, M_ / 128, 1), 256, SMEM_SZ>>>(
        pAf, pDyH, nullptr, pYf, pXf,
        N_, D_, D_, 0, 0, 0, 0, 1);

    // G3 (fp16, split-K x2): o_p = (1024y) @ (64E)^T -> g_O partials (65536*o)
    mma_nt<EPI_NONE><<<dim3(D_ / 256, M_ / 128, 2), 256, SMEM_SZ>>>(
        pYf, pEH, pO, nullptr, nullptr,
        D_, N_, N_ / 2, 0, 0, 0, (long)M_ * D_, 1);

    // out = LN((sum of 2 partials) / 65536)
    ln_rows<0, 2><<<M_, 256>>>(pO, out, nullptr, nullptr, 1.f / 65536.f);
}

// round 16
// speedup vs baseline: 1.1087x; 1.0191x over previous
#include <cuda_runtime.h>
#include <cuda_fp16.h>
#include <cstdint>

#define B_   32
#define T_   256
#define N_   4096
#define D_   256
#define M_   (B_ * T_)
#define EPSF 1e-6f
#define DECF 0.97f

// ---------------- scratch (device globals; no allocation) ----------------
__device__ float g_CS[M_];
__device__ float g_Cc[M_];
__device__ float g_S [4LL * B_ * T_ * T_];      // 4 split-K partials of 65536*scores
__device__ float g_A [M_ * D_];                 // 256*a*
__device__ float g_O [2LL * M_ * D_];           // 2 split-K partials of G3
__device__ float g_DEC[T_];                     // 0.97^L / 256 (decay_conv)

// fp16 operands; scalings: v,Dx x16; Dy,E x64; P,x x256; y x1024; S' = 256*raw*dec
__device__ __half g_Vf [M_ * D_];                             // 16*emb[idx]
__device__ __half g_DxH[N_ * D_];                             // 16*Dx
__device__ __half g_DyH[N_ * D_];                             // 64*Dy
__device__ __half g_EH [D_ * N_];                             // 64*E
__device__ __half g_Uh [M_ * D_];                             // LN(v) fp16 [b,s][d]
__device__ __half g_UT [M_ * D_];                             // transposed [b][d][s]
__device__ __half g_Sf [(long long)B_ * T_ * T_];             // decayed fp16 scores
__device__ __half g_Af [M_ * D_];                             // LN(a*) fp16
__device__ __half g_Xf [(long long)M_ * N_];                  // 256*x fp16
__device__ __half g_Yf [(long long)M_ * N_];                  // 256*P, then 1024*y fp16

// ---------------- PTX helpers (baseline ISA only) ----------------
__device__ __forceinline__ uint32_t smem_u32(const void* p) {
    uint32_t a;
    asm("{ .reg .u64 t; cvta.to.shared.u64 t, %1; cvt.u32.u64 %0, t; }" : "=r"(a) : "l"(p));
    return a;
}
__device__ __forceinline__ void cp16(uint32_t so, const void* g) {
    asm volatile("cp.async.cg.shared.global [%0], [%1], 16;" :: "r"(so), "l"(g));
}
__device__ __forceinline__ void cp_commit() {
    asm volatile("cp.async.commit_group;" ::: "memory");
}
template <int NN>
__device__ __forceinline__ void cp_wait() {
    asm volatile("cp.async.wait_group %0;" :: "n"(NN) : "memory");
}
__device__ __forceinline__ void ldsm_x4(uint32_t* f, uint32_t a) {
    asm volatile("ldmatrix.sync.aligned.m8n8.x4.shared.b16 {%0,%1,%2,%3}, [%4];"
        : "=r"(f[0]), "=r"(f[1]), "=r"(f[2]), "=r"(f[3]) : "r"(a));
}
__device__ __forceinline__ void mma_f16(float* c, const uint32_t* a, const uint32_t* b) {
    asm volatile("mma.sync.aligned.m16n8k16.row.col.f32.f16.f16.f32 "
        "{%0,%1,%2,%3}, {%4,%5,%6,%7}, {%8,%9}, {%0,%1,%2,%3};"
        : "+f"(c[0]), "+f"(c[1]), "+f"(c[2]), "+f"(c[3])
        : "r"(a[0]), "r"(a[1]), "r"(a[2]), "r"(a[3]), "r"(b[0]), "r"(b[1]));
}

// -- Main HMMA NT GEMM: CTA 128x256, warp 64x64, cross-chunk fragment pipelining
enum { EPI_NONE = 0, EPI_RELUH = 1, EPI_RELUMULX = 2 };

#define TILE_A  8192
#define TILE_BT 16384
#define STAGE_B (TILE_A + TILE_BT)
#define NSTG    4
#define SMEM_SZ (NSTG * STAGE_B)     // 98304

template <int EPI>
__global__ void __launch_bounds__(256, 1) mma_nt(
    const __half* __restrict__ Ah, const __half* __restrict__ Bh,
    float* __restrict__ Cf, __half* __restrict__ Ch,
    const __half* __restrict__ Xf,
    int Nd, int K, int kLen, long sA, long sB, long sC, long splitStride, int batches)
{
    extern __shared__ char smem[];
    const uint32_t sb = smem_u32(smem);
    const int tid  = threadIdx.x;
    const int lane = tid & 31;
    const int wid  = tid >> 5;
    const int wm   = wid >> 2;
    const int wn   = wid & 3;
    const int zz   = blockIdx.z;
    const int split = zz / batches;
    const int bz    = zz - split * batches;
    const long kOff = (long)split * kLen;
    const int bm = blockIdx.y * 128;
    const int bn = blockIdx.x * 256;

    float acc[4][8][4];
#pragma unroll
    for (int i = 0; i < 4; i++)
#pragma unroll
        for (int j = 0; j < 8; j++)
#pragma unroll
            for (int v = 0; v < 4; v++) acc[i][j][v] = 0.f;

    {
        const __half* Ahp = Ah + (long)bz * sA + (long)bm * K + kOff;
        const __half* Bhp = Bh + (long)bz * sB + (long)bn * K + kOff;

        const int qr0 = tid >> 2;
        const int qc0 = tid & 3;
        auto stage_load = [&](int stg, int k0) {
            uint32_t base = sb + stg * STAGE_B;
#pragma unroll
            for (int i = 0; i < 2; i++) {
                int r = qr0 + i * 64;
                uint32_t so = (uint32_t)(r * 64 + ((qc0 ^ ((r >> 1) & 3)) * 16));
                cp16(base + so, Ahp + (long)r * K + k0 + qc0 * 8);
            }
#pragma unroll
            for (int i = 0; i < 4; i++) {
                int r = qr0 + i * 64;
                uint32_t so = (uint32_t)(r * 64 + ((qc0 ^ ((r >> 1) & 3)) * 16));
                cp16(base + TILE_A + so, Bhp + (long)r * K + k0 + qc0 * 8);
            }
            cp_commit();
        };

        const int nC = kLen / 32;
        stage_load(0, 0);
        stage_load(1, 32);
        stage_load(2, 64);

        const uint32_t aRow  = (uint32_t)(wm * 64 + (lane & 15));
        const uint32_t aColG = (uint32_t)(lane >> 4);
        const uint32_t bRow  = (uint32_t)(wn * 64 + ((lane >> 4) << 3) + (lane & 7));
        const uint32_t bColG = (uint32_t)((lane >> 3) & 1);
        const uint32_t sa  = (aRow >> 1) & 3;
        const uint32_t sbw = (bRow >> 1) & 3;
        uint32_t aoff[2], boff[2];
#pragma unroll
        for (int ks = 0; ks < 2; ks++) {
            aoff[ks] = aRow * 64 + (((ks * 2 + aColG) ^ sa) * 16);
            boff[ks] = bRow * 64 + (((ks * 2 + bColG) ^ sbw) * 16);
        }

        uint32_t fA0[4][4], fB0[4][4], fA1[4][4], fB1[4][4];

        cp_wait<2>();
        __syncthreads();
#pragma unroll
        for (int ma = 0; ma < 4; ma++)
            ldsm_x4(fA0[ma], sb + aoff[0] + ma * 1024);
#pragma unroll
        for (int p = 0; p < 4; p++)
            ldsm_x4(fB0[p], sb + TILE_A + boff[0] + p * 1024);

        int stg = 0;
        for (int c = 0; c < nC; c++) {
            __syncthreads();
            if (c + 3 < nC) {
                int ns = stg + 3; if (ns >= NSTG) ns -= NSTG;
                stage_load(ns, (c + 3) * 32);
            } else {
                cp_commit();
            }

            const uint32_t st = sb + stg * STAGE_B;
#pragma unroll
            for (int ma = 0; ma < 4; ma++)
                ldsm_x4(fA1[ma], st + aoff[1] + ma * 1024);
#pragma unroll
            for (int p = 0; p < 4; p++)
                ldsm_x4(fB1[p], st + TILE_A + boff[1] + p * 1024);
#pragma unroll
            for (int ma = 0; ma < 4; ma++)
#pragma unroll
                for (int na = 0; na < 8; na++)
                    mma_f16(acc[ma][na], fA0[ma], &fB0[na >> 1][2 * (na & 1)]);

            cp_wait<2>();
            int nstg = stg + 1; if (nstg >= NSTG) nstg = 0;
            if (c + 1 < nC) {
                const uint32_t st2 = sb + nstg * STAGE_B;
#pragma unroll
                for (int ma = 0; ma < 4; ma++)
                    ldsm_x4(fA0[ma], st2 + aoff[0] + ma * 1024);
#pragma unroll
                for (int p = 0; p < 4; p++)
                    ldsm_x4(fB0[p], st2 + TILE_A + boff[0] + p * 1024);
            }
#pragma unroll
            for (int ma = 0; ma < 4; ma++)
#pragma unroll
                for (int na = 0; na < 8; na++)
                    mma_f16(acc[ma][na], fA1[ma], &fB1[na >> 1][2 * (na & 1)]);

            stg = nstg;
        }
    }

    float* Cfo = (EPI == EPI_NONE) ? (Cf + split * splitStride + (long)bz * sC) : nullptr;
    unsigned short* Ho = (EPI != EPI_NONE) ? reinterpret_cast<unsigned short*>(Ch) : nullptr;
    const int gr = lane >> 2;
    const int gc = (lane & 3) * 2;
#pragma unroll
    for (int ma = 0; ma < 4; ma++) {
#pragma unroll
        for (int half = 0; half < 2; half++) {
            const int row = bm + wm * 64 + ma * 16 + gr + half * 8;
            float rs = 0.f;
#pragma unroll
            for (int na = 0; na < 8; na++) {
                const int col = bn + wn * 64 + na * 8 + gc;
                float v0 = acc[ma][na][half * 2 + 0];
                float v1 = acc[ma][na][half * 2 + 1];
                long off = (long)row * Nd + col;
                if (EPI == EPI_RELUH) {
                    v0 = fmaxf(v0, 0.f); v1 = fmaxf(v1, 0.f);
                    rs += v0 + v1;
                    ushort2 o = make_ushort2(__half_as_ushort(__float2half_rn(v0)),
                                             __half_as_ushort(__float2half_rn(v1)));
                    *reinterpret_cast<ushort2*>(Ho + off) = o;
                } else if (EPI == EPI_RELUMULX) {
                    ushort2 xf = *reinterpret_cast<const ushort2*>(Xf + off);
                    float x0 = __half2float(__ushort_as_half(xf.x));
                    float x1 = __half2float(__ushort_as_half(xf.y));
                    v0 = fmaxf(v0, 0.f) * x0 * (1.f / 16.f);
                    v1 = fmaxf(v1, 0.f) * x1 * (1.f / 16.f);
                    ushort2 o = make_ushort2(__half_as_ushort(__float2half_rn(v0)),
                                             __half_as_ushort(__float2half_rn(v1)));
                    *reinterpret_cast<ushort2*>(Ho + off) = o;
                } else {
                    *reinterpret_cast<float2*>(Cfo + off) = make_float2(v0, v1);
                }
            }
            if (EPI == EPI_RELUH) {
                rs += __shfl_xor_sync(0xffffffffu, rs, 1);
                rs += __shfl_xor_sync(0xffffffffu, rs, 2);
                if ((lane & 3) == 0) atomicAdd(&g_CS[row], rs);
            }
        }
    }
}

// -- Scores: 128x128 tiles, triangular skip (early exit), split-K x4, 2 CTA/SM --
#define SK_TILE  8192
#define SK_STAGE (2 * SK_TILE)
#define SK_SMEM  (3 * SK_STAGE)      // 49152

__global__ void __launch_bounds__(256, 2) mma_sk(
    const __half* __restrict__ Xh, float* __restrict__ Cf, int kLen)
{
    const int bm = blockIdx.y * 128;
    const int bn = blockIdx.x * 128;
    // fully-masked tile (all cols > all rows): skip entirely; decay_conv masks it
    if (bn >= bm + 128) return;

    extern __shared__ char smem[];
    const uint32_t sb = smem_u32(smem);
    const int tid  = threadIdx.x;
    const int lane = tid & 31;
    const int wid  = tid >> 5;
    const int wm   = wid >> 2;
    const int wn   = wid & 3;
    const int zz   = blockIdx.z;
    const int split = zz >> 5;       // 0..3
    const int bz    = zz & 31;
    const long kOff = (long)split * kLen;

    float acc[4][4][4];
#pragma unroll
    for (int i = 0; i < 4; i++)
#pragma unroll
        for (int j = 0; j < 4; j++)
#pragma unroll
            for (int v = 0; v < 4; v++) acc[i][j][v] = 0.f;

    {
        const __half* Ahp = Xh + (long)bz * T_ * N_ + (long)bm * N_ + kOff;
        const __half* Bhp = Xh + (long)bz * T_ * N_ + (long)bn * N_ + kOff;

        const int qr0 = tid >> 2;
        const int qc0 = tid & 3;
        auto stage_load = [&](int stg, int k0) {
            uint32_t base = sb + stg * SK_STAGE;
#pragma unroll
            for (int i = 0; i < 2; i++) {
                int r = qr0 + i * 64;
                uint32_t so = (uint32_t)(r * 64 + ((qc0 ^ ((r >> 1) & 3)) * 16));
                long gofs = (long)r * N_ + k0 + qc0 * 8;
                cp16(base + so, Ahp + gofs);
                cp16(base + SK_TILE + so, Bhp + gofs);
            }
            cp_commit();
        };

        const int nC = kLen / 32;
        stage_load(0, 0);
        stage_load(1, 32);

        const uint32_t aRow  = (uint32_t)(wm * 64 + (lane & 15));
        const uint32_t aColG = (uint32_t)(lane >> 4);
        const uint32_t bRow  = (uint32_t)(wn * 32 + ((lane >> 4) << 3) + (lane & 7));
        const uint32_t bColG = (uint32_t)((lane >> 3) & 1);
        const uint32_t sa  = (aRow >> 1) & 3;
        const uint32_t sbw = (bRow >> 1) & 3;
        uint32_t aoff[2], boff[2];
#pragma unroll
        for (int ks = 0; ks < 2; ks++) {
            aoff[ks] = aRow * 64 + (((ks * 2 + aColG) ^ sa) * 16);
            boff[ks] = bRow * 64 + (((ks * 2 + bColG) ^ sbw) * 16);
        }

        int stg = 0;
        for (int c = 0; c < nC; c++) {
            cp_wait<1>();
            __syncthreads();
            if (c + 2 < nC) {
                int ns = stg + 2; if (ns >= 3) ns -= 3;
                stage_load(ns, (c + 2) * 32);
            } else {
                cp_commit();
            }

            const uint32_t st = sb + stg * SK_STAGE;
#pragma unroll
            for (int ks = 0; ks < 2; ks++) {
                uint32_t fA[4][4], fB[2][4];
#pragma unroll
                for (int ma = 0; ma < 4; ma++)
                    ldsm_x4(fA[ma], st + aoff[ks] + ma * 1024);
#pragma unroll
                for (int p = 0; p < 2; p++)
                    ldsm_x4(fB[p], st + SK_TILE + boff[ks] + p * 1024);
#pragma unroll
                for (int ma = 0; ma < 4; ma++)
#pragma unroll
                    for (int na = 0; na < 4; na++)
                        mma_f16(acc[ma][na], fA[ma], &fB[na >> 1][2 * (na & 1)]);
            }
            stg = (stg == 2) ? 0 : stg + 1;
        }
    }

    float* Cfo = Cf + (long)split * B_ * T_ * T_ + (long)bz * T_ * T_;
    const int gr = lane >> 2;
    const int gc = (lane & 3) * 2;
#pragma unroll
    for (int ma = 0; ma < 4; ma++) {
#pragma unroll
        for (int half = 0; half < 2; half++) {
            const int row = bm + wm * 64 + ma * 16 + gr + half * 8;
#pragma unroll
            for (int na = 0; na < 4; na++) {
                const int col = bn + wn * 32 + na * 8 + gc;
                *reinterpret_cast<float2*>(Cfo + (long)row * T_ + col) =
                    make_float2(acc[ma][na][half * 2 + 0], acc[ma][na][half * 2 + 1]);
            }
        }
    }
}

// -- a* HMMA: 128x128 tiles, 3-stage, 2 CTA/SM; A=S'(fp16), B=UT(fp16), C=fp32 --
#define AK_TILE  8192
#define AK_STAGE (2 * AK_TILE)
#define AK_SMEM  (3 * AK_STAGE)      // 49152

__global__ void __launch_bounds__(256, 2) mma_a(
    const __half* __restrict__ Sa, const __half* __restrict__ Ut,
    float* __restrict__ Cf)
{
    extern __shared__ char smem[];
    const uint32_t sb = smem_u32(smem);
    const int tid  = threadIdx.x;
    const int lane = tid & 31;
    const int wid  = tid >> 5;
    const int wm   = wid >> 2;
    const int wn   = wid & 3;
    const int bz = blockIdx.z;
    const int bm = blockIdx.y * 128;
    const int bn = blockIdx.x * 128;

    float acc[4][4][4];
#pragma unroll
    for (int i = 0; i < 4; i++)
#pragma unroll
        for (int j = 0; j < 4; j++)
#pragma unroll
            for (int v = 0; v < 4; v++) acc[i][j][v] = 0.f;

    {
        const __half* Ahp = Sa + (long)bz * T_ * T_ + (long)bm * T_;
        const __half* Bhp = Ut + (long)bz * D_ * T_ + (long)bn * T_;

        const int qr0 = tid >> 2;
        const int qc0 = tid & 3;
        auto stage_load = [&](int stg, int k0) {
            uint32_t base = sb + stg * AK_STAGE;
#pragma unroll
            for (int i = 0; i < 2; i++) {
                int r = qr0 + i * 64;
                uint32_t so = (uint32_t)(r * 64 + ((qc0 ^ ((r >> 1) & 3)) * 16));
                long gofs = (long)r * T_ + k0 + qc0 * 8;
                cp16(base + so, Ahp + gofs);
                cp16(base + AK_TILE + so, Bhp + gofs);
            }
            cp_commit();
        };

        const int nC = T_ / 32;
        stage_load(0, 0);
        stage_load(1, 32);

        const uint32_t aRow  = (uint32_t)(wm * 64 + (lane & 15));
        const uint32_t aColG = (uint32_t)(lane >> 4);
        const uint32_t bRow  = (uint32_t)(wn * 32 + ((lane >> 4) << 3) + (lane & 7));
        const uint32_t bColG = (uint32_t)((lane >> 3) & 1);
        const uint32_t sa  = (aRow >> 1) & 3;
        const uint32_t sbw = (bRow >> 1) & 3;
        uint32_t aoff[2], boff[2];
#pragma unroll
        for (int ks = 0; ks < 2; ks++) {
            aoff[ks] = aRow * 64 + (((ks * 2 + aColG) ^ sa) * 16);
            boff[ks] = bRow * 64 + (((ks * 2 + bColG) ^ sbw) * 16);
        }

        int stg = 0;
        for (int c = 0; c < nC; c++) {
            cp_wait<1>();
            __syncthreads();
            if (c + 2 < nC) {
                int ns = stg + 2; if (ns >= 3) ns -= 3;
                stage_load(ns, (c + 2) * 32);
            } else {
                cp_commit();
            }

            const uint32_t st = sb + stg * AK_STAGE;
#pragma unroll
            for (int ks = 0; ks < 2; ks++) {
                uint32_t fA[4][4], fB[2][4];
#pragma unroll
                for (int ma = 0; ma < 4; ma++)
                    ldsm_x4(fA[ma], st + aoff[ks] + ma * 1024);
#pragma unroll
                for (int p = 0; p < 2; p++)
                    ldsm_x4(fB[p], st + AK_TILE + boff[ks] + p * 1024);
#pragma unroll
                for (int ma = 0; ma < 4; ma++)
#pragma unroll
                    for (int na = 0; na < 4; na++)
                        mma_f16(acc[ma][na], fA[ma], &fB[na >> 1][2 * (na & 1)]);
            }
            stg = (stg == 2) ? 0 : stg + 1;
        }
    }

    float* Cfo = Cf + (long)bz * T_ * D_;
    const int gr = lane >> 2;
    const int gc = (lane & 3) * 2;
#pragma unroll
    for (int ma = 0; ma < 4; ma++) {
#pragma unroll
        for (int half = 0; half < 2; half++) {
            const int row = bm + wm * 64 + ma * 16 + gr + half * 8;
#pragma unroll
            for (int na = 0; na < 4; na++) {
                const int col = bn + wn * 32 + na * 8 + gc;
                *reinterpret_cast<float2*>(Cfo + (long)row * D_ + col) =
                    make_float2(acc[ma][na][half * 2 + 0], acc[ma][na][half * 2 + 1]);
            }
        }
    }
}

// ---------------- elementwise / scan / LN kernels ----------------
__device__ __forceinline__ float blockReduceSum256(float v) {
    __shared__ float sh[8];
    __syncthreads();
    int lane = threadIdx.x & 31;
    int w = threadIdx.x >> 5;
#pragma unroll
    for (int o = 16; o > 0; o >>= 1) v += __shfl_down_sync(0xffffffffu, v, o);
    if (lane == 0) sh[w] = v;
    __syncthreads();
    if (w == 0) {
        float t = (lane < 8) ? sh[lane] : 0.f;
#pragma unroll
        for (int o = 4; o > 0; o >>= 1) t += __shfl_down_sync(0xffffffffu, t, o);
        if (lane == 0) sh[0] = t;
    }
    __syncthreads();
    return sh[0];
}

// fused: weight conversions, emb gather, U = LN(emb[idx]) -> fp16, g_CS zero, g_DEC
__global__ void conv_gather_uln(const float* __restrict__ Dx, const float* __restrict__ Dy,
                                const float* __restrict__ E, const float* __restrict__ emb,
                                const int* __restrict__ idx)
{
    int blk = blockIdx.x;
    if (blk < 3072) {
        const float* src;
        __half* hi;
        float scale;
        int local;
        if (blk < 1024)      { src = Dx; hi = g_DxH; scale = 16.f; local = blk; }
        else if (blk < 2048) { src = Dy; hi = g_DyH; scale = 64.f; local = blk - 1024; }
        else                 { src = E;  hi = g_EH;  scale = 64.f; local = blk - 2048; }
        long i = (long)local * 256 + threadIdx.x;
        float4 v = reinterpret_cast<const float4*>(src)[i];
        ushort4 o = make_ushort4(
            __half_as_ushort(__float2half_rn(v.x * scale)),
            __half_as_ushort(__float2half_rn(v.y * scale)),
            __half_as_ushort(__float2half_rn(v.z * scale)),
            __half_as_ushort(__float2half_rn(v.w * scale)));
        reinterpret_cast<ushort4*>(hi)[i] = o;
        if (blk == 0 && threadIdx.x == 0) {
            float d = 1.f;
            for (int t = 0; t < T_; t++) { g_DEC[t] = d * (1.f / 256.f); d *= DECF; }
        }
    } else if (blk < 3072 + M_ / 4) {
        int m = (blk - 3072) * 4 + (threadIdx.x >> 6);
        int t = threadIdx.x & 63;
        if (t == 0) g_CS[m] = 0.f;
        float4 v = *reinterpret_cast<const float4*>(emb + (long)idx[m] * D_ + t * 4);
        ushort4 o = make_ushort4(
            __half_as_ushort(__float2half_rn(v.x * 16.f)),
            __half_as_ushort(__float2half_rn(v.y * 16.f)),
            __half_as_ushort(__float2half_rn(v.z * 16.f)),
            __half_as_ushort(__float2half_rn(v.w * 16.f)));
        reinterpret_cast<ushort4*>(g_Vf)[(long)m * (D_ / 4) + t] = o;
    } else {
        // U = LN(emb[idx[m]]) -> fp16
        int m = blk - (3072 + M_ / 4);
        long r = (long)idx[m];
        float z = emb[r * D_ + threadIdx.x];
        float mean = blockReduceSum256(z) * (1.f / D_);
        float d = z - mean;
        float var = blockReduceSum256(d * d) * (1.f / (D_ - 1));
        float v = d / (sqrtf(var) + EPSF);
        reinterpret_cast<unsigned short*>(g_Uh)[(long)m * D_ + threadIdx.x] =
            __half_as_ushort(__float2half_rn(v));
    }
}

__global__ void screc_kernel() {
    __shared__ float cs[B_ * T_];
    for (int i = threadIdx.x; i < B_ * T_; i += 256) {
        int t = i >> 5, b = i & 31;
        cs[t * 32 + b] = g_CS[b * T_ + t] * (1.f / 256.f);
    }
    __syncthreads();
    if (threadIdx.x < B_) {
        int b = threadIdx.x;
        float sprev = 0.f;
#pragma unroll 8
        for (int t = 0; t < T_; t++) {
            float sumx = __fdividef(sprev, sprev + EPSF);
            float s = DECF * sumx + cs[t * 32 + b];
            g_Cc[b * T_ + t] = __fdividef(1.f, s + EPSF);
            sprev = s;
        }
    }
}

__global__ void xrecur_kernel() {
    int b = blockIdx.y;
    int n = blockIdx.x * 256 + threadIdx.x;
    __shared__ float sc[T_];
    sc[threadIdx.x] = g_Cc[b * T_ + threadIdx.x];
    __syncthreads();
    float X = 0.f;
    long base = (long)b * T_ * N_ + n;
#pragma unroll 4
    for (int t = 0; t < T_; t++) {
        float p = __half2float(g_Yf[base + (long)t * N_]);
        X = (DECF * X + p) * sc[t];
        g_Xf[base + (long)t * N_] = __float2half_rn(X);
    }
}

// fused post-scores: transU (blocks [0,2048)) + decay/mask/fp16 (blocks [2048,4096))
__global__ void post_scores_kernel()
{
    int blk = blockIdx.x;
    int tid = threadIdx.x;
    if (blk < 2048) {
        __shared__ unsigned short tl[32][33];
        int b  = blk >> 6;
        int rem = blk & 63;
        int s0 = (rem & 7) * 32;
        int d0 = (rem >> 3) * 32;
        int tx = tid & 31, ty = tid >> 5;
        const unsigned short* src = reinterpret_cast<const unsigned short*>(g_Uh);
        unsigned short* dst = reinterpret_cast<unsigned short*>(g_UT);
#pragma unroll
        for (int i = ty; i < 32; i += 8)
            tl[i][tx] = src[((long)b * T_ + s0 + i) * D_ + d0 + tx];
        __syncthreads();
#pragma unroll
        for (int i = ty; i < 32; i += 8)
            dst[(long)b * D_ * T_ + (long)(d0 + i) * T_ + s0 + tx] = tl[tx][i];
    } else {
        // S' = (S0+S1+S2+S3) * dec^(t-s)/256, 0 for s >= t
        int m = (blk - 2048) * 4 + (tid >> 6);   // (b,t)
        int t = m & (T_ - 1);
        int s0 = (tid & 63) * 4;
        long o = (long)m * T_ + s0;
        const float* S = g_S;
        const long P = (long)B_ * T_ * T_;
        float4 a0 = *reinterpret_cast<const float4*>(S + o);
        float4 a1 = *reinterpret_cast<const float4*>(S + P + o);
        float4 a2 = *reinterpret_cast<const float4*>(S + 2 * P + o);
        float4 a3 = *reinterpret_cast<const float4*>(S + 3 * P + o);
        float vv[4] = {a0.x + a1.x + a2.x + a3.x, a0.y + a1.y + a2.y + a3.y,
                       a0.z + a1.z + a2.z + a3.z, a0.w + a1.w + a2.w + a3.w};
        unsigned short os[4];
#pragma unroll
        for (int j = 0; j < 4; j++) {
            int L = t - (s0 + j);
            float v = (L > 0) ? vv[j] * g_DEC[L] : 0.f;
            os[j] = __half_as_ushort(__float2half_rn(v));
        }
        *reinterpret_cast<ushort4*>(reinterpret_cast<unsigned short*>(g_Sf) + o) =
            make_ushort4(os[0], os[1], os[2], os[3]);
    }
}

// OUT: 0 = fp32, 1 = fp16 single
template <int OUT, int NPART>
__global__ void ln_rows(const float* __restrict__ in, float* __restrict__ outf,
                        unsigned short* __restrict__ oh, float inscale)
{
    int m = blockIdx.x;
    float z = in[(long)m * D_ + threadIdx.x];
#pragma unroll
    for (int p = 1; p < NPART; p++)
        z += in[(long)p * M_ * D_ + (long)m * D_ + threadIdx.x];
    z *= inscale;
    float mean = blockReduceSum256(z) * (1.f / D_);
    float d = z - mean;
    float var = blockReduceSum256(d * d) * (1.f / (D_ - 1));
    float v = d / (sqrtf(var) + EPSF);
    long o = (long)m * D_ + threadIdx.x;
    if (OUT == 1) {
        oh[o] = __half_as_ushort(__float2half_rn(v));
    } else {
        outf[o] = v;
    }
}

// ---------------- launch ----------------
extern "C" void kernel_launch(void* const* d_in, const int* in_sizes, int n_in,
                              void* d_out, int out_size)
{
    (void)in_sizes; (void)n_in; (void)out_size;
    const int*   idx  = (const int*)d_in[0];
    const float* temb = (const float*)d_in[1];
    const float* E    = (const float*)d_in[2];
    const float* Dx   = (const float*)d_in[3];
    const float* Dy   = (const float*)d_in[4];
    float* out = (float*)d_out;

    float *pS, *pA, *pO;
    __half *pVf, *pDxH, *pDyH, *pEH, *pUT, *pSf, *pAf, *pXf, *pYf;
    cudaGetSymbolAddress((void**)&pS,  g_S);
    cudaGetSymbolAddress((void**)&pA,  g_A);
    cudaGetSymbolAddress((void**)&pO,  g_O);
    cudaGetSymbolAddress((void**)&pVf, g_Vf);
    cudaGetSymbolAddress((void**)&pDxH, g_DxH);
    cudaGetSymbolAddress((void**)&pDyH, g_DyH);
    cudaGetSymbolAddress((void**)&pEH, g_EH);
    cudaGetSymbolAddress((void**)&pUT, g_UT);
    cudaGetSymbolAddress((void**)&pSf, g_Sf);
    cudaGetSymbolAddress((void**)&pAf, g_Af);
    cudaGetSymbolAddress((void**)&pXf, g_Xf);
    cudaGetSymbolAddress((void**)&pYf, g_Yf);

    cudaFuncSetAttribute(mma_nt<EPI_RELUH>,
                         cudaFuncAttributeMaxDynamicSharedMemorySize, SMEM_SZ);
    cudaFuncSetAttribute(mma_nt<EPI_NONE>,
                         cudaFuncAttributeMaxDynamicSharedMemorySize, SMEM_SZ);
    cudaFuncSetAttribute(mma_nt<EPI_RELUMULX>,
                         cudaFuncAttributeMaxDynamicSharedMemorySize, SMEM_SZ);
    cudaFuncSetAttribute(mma_sk,
                         cudaFuncAttributeMaxDynamicSharedMemorySize, SK_SMEM);
    cudaFuncSetAttribute(mma_a,
                         cudaFuncAttributeMaxDynamicSharedMemorySize, AK_SMEM);

    // fused conversions + gather + U-LN (+g_DEC, +g_CS zero)
    conv_gather_uln<<<3072 + M_ / 4 + M_, 256>>>(Dx, Dy, E, temb, idx);

    // G1 (fp16): 256*P = relu((16v) @ (16Dx)^T) -> g_Yf, row-sum -> g_CS
    mma_nt<EPI_RELUH><<<dim3(N_ / 256, M_ / 128, 1), 256, SMEM_SZ>>>(
        pVf, pDxH, nullptr, pYf, nullptr,
        N_, D_, D_, 0, 0, 0, 0, 1);

    screc_kernel<<<1, 256>>>();
    xrecur_kernel<<<dim3(N_ / 256, B_, 1), 256>>>();

    // scores (65536*raw, split-K x4, triangular skip, fp16)
    mma_sk<<<dim3(T_ / 128, T_ / 128, 4 * B_), 256, SK_SMEM>>>(pXf, pS, N_ / 4);

    // transU + decay/mask -> fp16 S'
    post_scores_kernel<<<2048 + M_ / 4, 256>>>();

    // 256*a* = S' @ UT (HMMA)
    mma_a<<<dim3(D_ / 128, T_ / 128, B_), 256, AK_SMEM>>>(pSf, pUT, pA);

    // a* <- LN(a*) with exact 1/256 unscale -> fp16
    ln_rows<1, 1><<<M_, 256>>>(pA, nullptr, (unsigned short*)pAf, 1.f / 256.f);

    // G2 (fp16): 1024y = relu(LN(a*) @ (64Dy)^T) * (256x) / 16 -> g_Yf
    mma_nt<EPI_RELUMULX><<<dim3(N_ / 256, M_ / 128, 1), 256, SMEM_SZ>>>(
        pAf, pDyH, nullptr, pYf, pXf,
        N_, D_, D_, 0, 0, 0, 0, 1);

    // G3 (fp16, split-K x2): o_p = (1024y) @ (64E)^T -> g_O partials (65536*o)
    mma_nt<EPI_NONE><<<dim3(D_ / 256, M_ / 128, 2), 256, SMEM_SZ>>>(
        pYf, pEH, pO, nullptr, nullptr,
        D_, N_, N_ / 2, 0, 0, 0, (long)M_ * D_, 1);

    // out = LN((sum of 2 partials) / 65536)
    ln_rows<0, 2><<<M_, 256>>>(pO, out, nullptr, 1.f / 65536.f);
}

// round 17
// speedup vs baseline: 1.1098x; 1.0010x over previous
#include <cuda_runtime.h>
#include <cuda_fp16.h>
#include <cstdint>

#define B_   32
#define T_   256
#define N_   4096
#define D_   256
#define M_   (B_ * T_)
#define EPSF 1e-6f
#define DECF 0.97f

// ---------------- scratch (device globals; no allocation) ----------------
__device__ float g_CS[M_];
__device__ float g_Cc[M_];
__device__ float g_S [4LL * B_ * T_ * T_];      // 4 split-K partials of 65536*scores
__device__ float g_A [M_ * D_];                 // 256*a*
__device__ float g_O [2LL * M_ * D_];           // 2 split-K partials of G3
__device__ float g_DEC[T_];                     // 0.97^L / 256 (decay_conv)

// fp16 operands; scalings: v,Dx x16; Dy,E x64; P,x x256; y x1024; S' = 256*raw*dec
__device__ __half g_Vf [M_ * D_];                             // 16*emb[idx]
__device__ __half g_DxH[N_ * D_];                             // 16*Dx
__device__ __half g_DyH[N_ * D_];                             // 64*Dy
__device__ __half g_EH [D_ * N_];                             // 64*E
__device__ __half g_Uh [M_ * D_];                             // LN(v) fp16 [b,s][d]
__device__ __half g_UT [M_ * D_];                             // transposed [b][d][s]
__device__ __half g_Sf [(long long)B_ * T_ * T_];             // decayed fp16 scores
__device__ __half g_Af [M_ * D_];                             // LN(a*) fp16
__device__ __half g_Xf [(long long)M_ * N_];                  // 256*x fp16
__device__ __half g_Yf [(long long)M_ * N_];                  // 256*P, then 1024*y fp16

// ---------------- PTX helpers (baseline ISA only) ----------------
__device__ __forceinline__ uint32_t smem_u32(const void* p) {
    uint32_t a;
    asm("{ .reg .u64 t; cvta.to.shared.u64 t, %1; cvt.u32.u64 %0, t; }" : "=r"(a) : "l"(p));
    return a;
}
__device__ __forceinline__ void cp16(uint32_t so, const void* g) {
    asm volatile("cp.async.cg.shared.global [%0], [%1], 16;" :: "r"(so), "l"(g));
}
__device__ __forceinline__ void cp_commit() {
    asm volatile("cp.async.commit_group;" ::: "memory");
}
template <int NN>
__device__ __forceinline__ void cp_wait() {
    asm volatile("cp.async.wait_group %0;" :: "n"(NN) : "memory");
}
__device__ __forceinline__ void ldsm_x4(uint32_t* f, uint32_t a) {
    asm volatile("ldmatrix.sync.aligned.m8n8.x4.shared.b16 {%0,%1,%2,%3}, [%4];"
        : "=r"(f[0]), "=r"(f[1]), "=r"(f[2]), "=r"(f[3]) : "r"(a));
}
__device__ __forceinline__ void mma_f16(float* c, const uint32_t* a, const uint32_t* b) {
    asm volatile("mma.sync.aligned.m16n8k16.row.col.f32.f16.f16.f32 "
        "{%0,%1,%2,%3}, {%4,%5,%6,%7}, {%8,%9}, {%0,%1,%2,%3};"
        : "+f"(c[0]), "+f"(c[1]), "+f"(c[2]), "+f"(c[3])
        : "r"(a[0]), "r"(a[1]), "r"(a[2]), "r"(a[3]), "r"(b[0]), "r"(b[1]));
}

// -- Main HMMA NT GEMM: CTA 128x256, warp 64x64, cross-chunk fragment pipelining
enum { EPI_NONE = 0, EPI_RELUH = 1, EPI_RELUMULX = 2 };

#define TILE_A  8192
#define TILE_BT 16384
#define STAGE_B (TILE_A + TILE_BT)
#define NSTG    4
#define SMEM_SZ (NSTG * STAGE_B)     // 98304

template <int EPI>
__global__ void __launch_bounds__(256, 1) mma_nt(
    const __half* __restrict__ Ah, const __half* __restrict__ Bh,
    float* __restrict__ Cf, __half* __restrict__ Ch,
    const __half* __restrict__ Xf,
    int Nd, int K, int kLen, long sA, long sB, long sC, long splitStride, int batches)
{
    extern __shared__ char smem[];
    const uint32_t sb = smem_u32(smem);
    const int tid  = threadIdx.x;
    const int lane = tid & 31;
    const int wid  = tid >> 5;
    const int wm   = wid >> 2;
    const int wn   = wid & 3;
    const int zz   = blockIdx.z;
    const int split = zz / batches;
    const int bz    = zz - split * batches;
    const long kOff = (long)split * kLen;
    const int bm = blockIdx.y * 128;
    const int bn = blockIdx.x * 256;

    float acc[4][8][4];
#pragma unroll
    for (int i = 0; i < 4; i++)
#pragma unroll
        for (int j = 0; j < 8; j++)
#pragma unroll
            for (int v = 0; v < 4; v++) acc[i][j][v] = 0.f;

    {
        const __half* Ahp = Ah + (long)bz * sA + (long)bm * K + kOff;
        const __half* Bhp = Bh + (long)bz * sB + (long)bn * K + kOff;

        const int qr0 = tid >> 2;
        const int qc0 = tid & 3;
        auto stage_load = [&](int stg, int k0) {
            uint32_t base = sb + stg * STAGE_B;
#pragma unroll
            for (int i = 0; i < 2; i++) {
                int r = qr0 + i * 64;
                uint32_t so = (uint32_t)(r * 64 + ((qc0 ^ ((r >> 1) & 3)) * 16));
                cp16(base + so, Ahp + (long)r * K + k0 + qc0 * 8);
            }
#pragma unroll
            for (int i = 0; i < 4; i++) {
                int r = qr0 + i * 64;
                uint32_t so = (uint32_t)(r * 64 + ((qc0 ^ ((r >> 1) & 3)) * 16));
                cp16(base + TILE_A + so, Bhp + (long)r * K + k0 + qc0 * 8);
            }
            cp_commit();
        };

        const int nC = kLen / 32;
        stage_load(0, 0);
        stage_load(1, 32);
        stage_load(2, 64);

        const uint32_t aRow  = (uint32_t)(wm * 64 + (lane & 15));
        const uint32_t aColG = (uint32_t)(lane >> 4);
        const uint32_t bRow  = (uint32_t)(wn * 64 + ((lane >> 4) << 3) + (lane & 7));
        const uint32_t bColG = (uint32_t)((lane >> 3) & 1);
        const uint32_t sa  = (aRow >> 1) & 3;
        const uint32_t sbw = (bRow >> 1) & 3;
        uint32_t aoff[2], boff[2];
#pragma unroll
        for (int ks = 0; ks < 2; ks++) {
            aoff[ks] = aRow * 64 + (((ks * 2 + aColG) ^ sa) * 16);
            boff[ks] = bRow * 64 + (((ks * 2 + bColG) ^ sbw) * 16);
        }

        uint32_t fA0[4][4], fB0[4][4], fA1[4][4], fB1[4][4];

        cp_wait<2>();
        __syncthreads();
#pragma unroll
        for (int ma = 0; ma < 4; ma++)
            ldsm_x4(fA0[ma], sb + aoff[0] + ma * 1024);
#pragma unroll
        for (int p = 0; p < 4; p++)
            ldsm_x4(fB0[p], sb + TILE_A + boff[0] + p * 1024);

        int stg = 0;
        for (int c = 0; c < nC; c++) {
            __syncthreads();
            if (c + 3 < nC) {
                int ns = stg + 3; if (ns >= NSTG) ns -= NSTG;
                stage_load(ns, (c + 3) * 32);
            } else {
                cp_commit();
            }

            const uint32_t st = sb + stg * STAGE_B;
#pragma unroll
            for (int ma = 0; ma < 4; ma++)
                ldsm_x4(fA1[ma], st + aoff[1] + ma * 1024);
#pragma unroll
            for (int p = 0; p < 4; p++)
                ldsm_x4(fB1[p], st + TILE_A + boff[1] + p * 1024);
#pragma unroll
            for (int ma = 0; ma < 4; ma++)
#pragma unroll
                for (int na = 0; na < 8; na++)
                    mma_f16(acc[ma][na], fA0[ma], &fB0[na >> 1][2 * (na & 1)]);

            cp_wait<2>();
            int nstg = stg + 1; if (nstg >= NSTG) nstg = 0;
            if (c + 1 < nC) {
                const uint32_t st2 = sb + nstg * STAGE_B;
#pragma unroll
                for (int ma = 0; ma < 4; ma++)
                    ldsm_x4(fA0[ma], st2 + aoff[0] + ma * 1024);
#pragma unroll
                for (int p = 0; p < 4; p++)
                    ldsm_x4(fB0[p], st2 + TILE_A + boff[0] + p * 1024);
            }
#pragma unroll
            for (int ma = 0; ma < 4; ma++)
#pragma unroll
                for (int na = 0; na < 8; na++)
                    mma_f16(acc[ma][na], fA1[ma], &fB1[na >> 1][2 * (na & 1)]);

            stg = nstg;
        }
    }

    float* Cfo = (EPI == EPI_NONE) ? (Cf + split * splitStride + (long)bz * sC) : nullptr;
    unsigned short* Ho = (EPI != EPI_NONE) ? reinterpret_cast<unsigned short*>(Ch) : nullptr;
    const int gr = lane >> 2;
    const int gc = (lane & 3) * 2;
#pragma unroll
    for (int ma = 0; ma < 4; ma++) {
#pragma unroll
        for (int half = 0; half < 2; half++) {
            const int row = bm + wm * 64 + ma * 16 + gr + half * 8;
            float rs = 0.f;
#pragma unroll
            for (int na = 0; na < 8; na++) {
                const int col = bn + wn * 64 + na * 8 + gc;
                float v0 = acc[ma][na][half * 2 + 0];
                float v1 = acc[ma][na][half * 2 + 1];
                long off = (long)row * Nd + col;
                if (EPI == EPI_RELUH) {
                    v0 = fmaxf(v0, 0.f); v1 = fmaxf(v1, 0.f);
                    rs += v0 + v1;
                    ushort2 o = make_ushort2(__half_as_ushort(__float2half_rn(v0)),
                                             __half_as_ushort(__float2half_rn(v1)));
                    *reinterpret_cast<ushort2*>(Ho + off) = o;
                } else if (EPI == EPI_RELUMULX) {
                    ushort2 xf = *reinterpret_cast<const ushort2*>(Xf + off);
                    float x0 = __half2float(__ushort_as_half(xf.x));
                    float x1 = __half2float(__ushort_as_half(xf.y));
                    v0 = fmaxf(v0, 0.f) * x0 * (1.f / 16.f);
                    v1 = fmaxf(v1, 0.f) * x1 * (1.f / 16.f);
                    ushort2 o = make_ushort2(__half_as_ushort(__float2half_rn(v0)),
                                             __half_as_ushort(__float2half_rn(v1)));
                    *reinterpret_cast<ushort2*>(Ho + off) = o;
                } else {
                    *reinterpret_cast<float2*>(Cfo + off) = make_float2(v0, v1);
                }
            }
            if (EPI == EPI_RELUH) {
                rs += __shfl_xor_sync(0xffffffffu, rs, 1);
                rs += __shfl_xor_sync(0xffffffffu, rs, 2);
                if ((lane & 3) == 0) atomicAdd(&g_CS[row], rs);
            }
        }
    }
}

// -- Scores: 128x128 tiles, triangular skip (early exit), split-K x4, 2 CTA/SM --
#define SK_TILE  8192
#define SK_STAGE (2 * SK_TILE)
#define SK_SMEM  (3 * SK_STAGE)      // 49152

__global__ void __launch_bounds__(256, 2) mma_sk(
    const __half* __restrict__ Xh, float* __restrict__ Cf, int kLen)
{
    const int bm = blockIdx.y * 128;
    const int bn = blockIdx.x * 128;
    if (bn >= bm + 128) return;      // fully-masked tile; decay_conv masks output

    extern __shared__ char smem[];
    const uint32_t sb = smem_u32(smem);
    const int tid  = threadIdx.x;
    const int lane = tid & 31;
    const int wid  = tid >> 5;
    const int wm   = wid >> 2;
    const int wn   = wid & 3;
    const int zz   = blockIdx.z;
    const int split = zz >> 5;
    const int bz    = zz & 31;
    const long kOff = (long)split * kLen;

    float acc[4][4][4];
#pragma unroll
    for (int i = 0; i < 4; i++)
#pragma unroll
        for (int j = 0; j < 4; j++)
#pragma unroll
            for (int v = 0; v < 4; v++) acc[i][j][v] = 0.f;

    {
        const __half* Ahp = Xh + (long)bz * T_ * N_ + (long)bm * N_ + kOff;
        const __half* Bhp = Xh + (long)bz * T_ * N_ + (long)bn * N_ + kOff;

        const int qr0 = tid >> 2;
        const int qc0 = tid & 3;
        auto stage_load = [&](int stg, int k0) {
            uint32_t base = sb + stg * SK_STAGE;
#pragma unroll
            for (int i = 0; i < 2; i++) {
                int r = qr0 + i * 64;
                uint32_t so = (uint32_t)(r * 64 + ((qc0 ^ ((r >> 1) & 3)) * 16));
                long gofs = (long)r * N_ + k0 + qc0 * 8;
                cp16(base + so, Ahp + gofs);
                cp16(base + SK_TILE + so, Bhp + gofs);
            }
            cp_commit();
        };

        const int nC = kLen / 32;
        stage_load(0, 0);
        stage_load(1, 32);

        const uint32_t aRow  = (uint32_t)(wm * 64 + (lane & 15));
        const uint32_t aColG = (uint32_t)(lane >> 4);
        const uint32_t bRow  = (uint32_t)(wn * 32 + ((lane >> 4) << 3) + (lane & 7));
        const uint32_t bColG = (uint32_t)((lane >> 3) & 1);
        const uint32_t sa  = (aRow >> 1) & 3;
        const uint32_t sbw = (bRow >> 1) & 3;
        uint32_t aoff[2], boff[2];
#pragma unroll
        for (int ks = 0; ks < 2; ks++) {
            aoff[ks] = aRow * 64 + (((ks * 2 + aColG) ^ sa) * 16);
            boff[ks] = bRow * 64 + (((ks * 2 + bColG) ^ sbw) * 16);
        }

        int stg = 0;
        for (int c = 0; c < nC; c++) {
            cp_wait<1>();
            __syncthreads();
            if (c + 2 < nC) {
                int ns = stg + 2; if (ns >= 3) ns -= 3;
                stage_load(ns, (c + 2) * 32);
            } else {
                cp_commit();
            }

            const uint32_t st = sb + stg * SK_STAGE;
#pragma unroll
            for (int ks = 0; ks < 2; ks++) {
                uint32_t fA[4][4], fB[2][4];
#pragma unroll
                for (int ma = 0; ma < 4; ma++)
                    ldsm_x4(fA[ma], st + aoff[ks] + ma * 1024);
#pragma unroll
                for (int p = 0; p < 2; p++)
                    ldsm_x4(fB[p], st + SK_TILE + boff[ks] + p * 1024);
#pragma unroll
                for (int ma = 0; ma < 4; ma++)
#pragma unroll
                    for (int na = 0; na < 4; na++)
                        mma_f16(acc[ma][na], fA[ma], &fB[na >> 1][2 * (na & 1)]);
            }
            stg = (stg == 2) ? 0 : stg + 1;
        }
    }

    float* Cfo = Cf + (long)split * B_ * T_ * T_ + (long)bz * T_ * T_;
    const int gr = lane >> 2;
    const int gc = (lane & 3) * 2;
#pragma unroll
    for (int ma = 0; ma < 4; ma++) {
#pragma unroll
        for (int half = 0; half < 2; half++) {
            const int row = bm + wm * 64 + ma * 16 + gr + half * 8;
#pragma unroll
            for (int na = 0; na < 4; na++) {
                const int col = bn + wn * 32 + na * 8 + gc;
                *reinterpret_cast<float2*>(Cfo + (long)row * T_ + col) =
                    make_float2(acc[ma][na][half * 2 + 0], acc[ma][na][half * 2 + 1]);
            }
        }
    }
}

// -- a* HMMA: 128x128 tiles, 3-stage, 2 CTA/SM; A=S'(fp16), B=UT(fp16), C=fp32 --
#define AK_TILE  8192
#define AK_STAGE (2 * AK_TILE)
#define AK_SMEM  (3 * AK_STAGE)      // 49152

__global__ void __launch_bounds__(256, 2) mma_a(
    const __half* __restrict__ Sa, const __half* __restrict__ Ut,
    float* __restrict__ Cf)
{
    extern __shared__ char smem[];
    const uint32_t sb = smem_u32(smem);
    const int tid  = threadIdx.x;
    const int lane = tid & 31;
    const int wid  = tid >> 5;
    const int wm   = wid >> 2;
    const int wn   = wid & 3;
    const int bz = blockIdx.z;
    const int bm = blockIdx.y * 128;
    const int bn = blockIdx.x * 128;

    float acc[4][4][4];
#pragma unroll
    for (int i = 0; i < 4; i++)
#pragma unroll
        for (int j = 0; j < 4; j++)
#pragma unroll
            for (int v = 0; v < 4; v++) acc[i][j][v] = 0.f;

    {
        const __half* Ahp = Sa + (long)bz * T_ * T_ + (long)bm * T_;
        const __half* Bhp = Ut + (long)bz * D_ * T_ + (long)bn * T_;

        const int qr0 = tid >> 2;
        const int qc0 = tid & 3;
        auto stage_load = [&](int stg, int k0) {
            uint32_t base = sb + stg * AK_STAGE;
#pragma unroll
            for (int i = 0; i < 2; i++) {
                int r = qr0 + i * 64;
                uint32_t so = (uint32_t)(r * 64 + ((qc0 ^ ((r >> 1) & 3)) * 16));
                long gofs = (long)r * T_ + k0 + qc0 * 8;
                cp16(base + so, Ahp + gofs);
                cp16(base + AK_TILE + so, Bhp + gofs);
            }
            cp_commit();
        };

        const int nC = T_ / 32;
        stage_load(0, 0);
        stage_load(1, 32);

        const uint32_t aRow  = (uint32_t)(wm * 64 + (lane & 15));
        const uint32_t aColG = (uint32_t)(lane >> 4);
        const uint32_t bRow  = (uint32_t)(wn * 32 + ((lane >> 4) << 3) + (lane & 7));
        const uint32_t bColG = (uint32_t)((lane >> 3) & 1);
        const uint32_t sa  = (aRow >> 1) & 3;
        const uint32_t sbw = (bRow >> 1) & 3;
        uint32_t aoff[2], boff[2];
#pragma unroll
        for (int ks = 0; ks < 2; ks++) {
            aoff[ks] = aRow * 64 + (((ks * 2 + aColG) ^ sa) * 16);
            boff[ks] = bRow * 64 + (((ks * 2 + bColG) ^ sbw) * 16);
        }

        int stg = 0;
        for (int c = 0; c < nC; c++) {
            cp_wait<1>();
            __syncthreads();
            if (c + 2 < nC) {
                int ns = stg + 2; if (ns >= 3) ns -= 3;
                stage_load(ns, (c + 2) * 32);
            } else {
                cp_commit();
            }

            const uint32_t st = sb + stg * AK_STAGE;
#pragma unroll
            for (int ks = 0; ks < 2; ks++) {
                uint32_t fA[4][4], fB[2][4];
#pragma unroll
                for (int ma = 0; ma < 4; ma++)
                    ldsm_x4(fA[ma], st + aoff[ks] + ma * 1024);
#pragma unroll
                for (int p = 0; p < 2; p++)
                    ldsm_x4(fB[p], st + AK_TILE + boff[ks] + p * 1024);
#pragma unroll
                for (int ma = 0; ma < 4; ma++)
#pragma unroll
                    for (int na = 0; na < 4; na++)
                        mma_f16(acc[ma][na], fA[ma], &fB[na >> 1][2 * (na & 1)]);
            }
            stg = (stg == 2) ? 0 : stg + 1;
        }
    }

    float* Cfo = Cf + (long)bz * T_ * D_;
    const int gr = lane >> 2;
    const int gc = (lane & 3) * 2;
#pragma unroll
    for (int ma = 0; ma < 4; ma++) {
#pragma unroll
        for (int half = 0; half < 2; half++) {
            const int row = bm + wm * 64 + ma * 16 + gr + half * 8;
#pragma unroll
            for (int na = 0; na < 4; na++) {
                const int col = bn + wn * 32 + na * 8 + gc;
                *reinterpret_cast<float2*>(Cfo + (long)row * D_ + col) =
                    make_float2(acc[ma][na][half * 2 + 0], acc[ma][na][half * 2 + 1]);
            }
        }
    }
}

// ---------------- elementwise / scan / LN kernels ----------------
__device__ __forceinline__ float blockReduceSum256(float v) {
    __shared__ float sh[8];
    __syncthreads();
    int lane = threadIdx.x & 31;
    int w = threadIdx.x >> 5;
#pragma unroll
    for (int o = 16; o > 0; o >>= 1) v += __shfl_down_sync(0xffffffffu, v, o);
    if (lane == 0) sh[w] = v;
    __syncthreads();
    if (w == 0) {
        float t = (lane < 8) ? sh[lane] : 0.f;
#pragma unroll
        for (int o = 4; o > 0; o >>= 1) t += __shfl_down_sync(0xffffffffu, t, o);
        if (lane == 0) sh[0] = t;
    }
    __syncthreads();
    return sh[0];
}

// fused: weight conversions, emb gather, U = LN(emb[idx]) -> fp16, g_CS zero, g_DEC
__global__ void conv_gather_uln(const float* __restrict__ Dx, const float* __restrict__ Dy,
                                const float* __restrict__ E, const float* __restrict__ emb,
                                const int* __restrict__ idx)
{
    int blk = blockIdx.x;
    if (blk < 3072) {
        const float* src;
        __half* hi;
        float scale;
        int local;
        if (blk < 1024)      { src = Dx; hi = g_DxH; scale = 16.f; local = blk; }
        else if (blk < 2048) { src = Dy; hi = g_DyH; scale = 64.f; local = blk - 1024; }
        else                 { src = E;  hi = g_EH;  scale = 64.f; local = blk - 2048; }
        long i = (long)local * 256 + threadIdx.x;
        float4 v = reinterpret_cast<const float4*>(src)[i];
        ushort4 o = make_ushort4(
            __half_as_ushort(__float2half_rn(v.x * scale)),
            __half_as_ushort(__float2half_rn(v.y * scale)),
            __half_as_ushort(__float2half_rn(v.z * scale)),
            __half_as_ushort(__float2half_rn(v.w * scale)));
        reinterpret_cast<ushort4*>(hi)[i] = o;
        if (blk == 0 && threadIdx.x == 0) {
            float d = 1.f;
            for (int t = 0; t < T_; t++) { g_DEC[t] = d * (1.f / 256.f); d *= DECF; }
        }
    } else if (blk < 3072 + M_ / 4) {
        int m = (blk - 3072) * 4 + (threadIdx.x >> 6);
        int t = threadIdx.x & 63;
        if (t == 0) g_CS[m] = 0.f;
        float4 v = *reinterpret_cast<const float4*>(emb + (long)idx[m] * D_ + t * 4);
        ushort4 o = make_ushort4(
            __half_as_ushort(__float2half_rn(v.x * 16.f)),
            __half_as_ushort(__float2half_rn(v.y * 16.f)),
            __half_as_ushort(__float2half_rn(v.z * 16.f)),
            __half_as_ushort(__float2half_rn(v.w * 16.f)));
        reinterpret_cast<ushort4*>(g_Vf)[(long)m * (D_ / 4) + t] = o;
    } else {
        int m = blk - (3072 + M_ / 4);
        long r = (long)idx[m];
        float z = emb[r * D_ + threadIdx.x];
        float mean = blockReduceSum256(z) * (1.f / D_);
        float d = z - mean;
        float var = blockReduceSum256(d * d) * (1.f / (D_ - 1));
        float v = d / (sqrtf(var) + EPSF);
        reinterpret_cast<unsigned short*>(g_Uh)[(long)m * D_ + threadIdx.x] =
            __half_as_ushort(__float2half_rn(v));
    }
}

__global__ void screc_kernel() {
    __shared__ float cs[B_ * T_];
    for (int i = threadIdx.x; i < B_ * T_; i += 256) {
        int t = i >> 5, b = i & 31;
        cs[t * 32 + b] = g_CS[b * T_ + t] * (1.f / 256.f);
    }
    __syncthreads();
    if (threadIdx.x < B_) {
        int b = threadIdx.x;
        float sprev = 0.f;
#pragma unroll 8
        for (int t = 0; t < T_; t++) {
            float sumx = __fdividef(sprev, sprev + EPSF);
            float s = DECF * sumx + cs[t * 32 + b];
            g_Cc[b * T_ + t] = __fdividef(1.f, s + EPSF);
            sprev = s;
        }
    }
}

// x scan: 2 independent columns per thread (half2), grid (N_/512, B_)
__global__ void xrecur_kernel() {
    int b = blockIdx.y;
    int n0 = blockIdx.x * 512 + threadIdx.x * 2;
    __shared__ float sc[T_];
    sc[threadIdx.x] = g_Cc[b * T_ + threadIdx.x];
    __syncthreads();
    float X0 = 0.f, X1 = 0.f;
    long base = (long)b * T_ * N_ + n0;
    const __half* Pp = g_Yf;
    __half* Xp = g_Xf;
#pragma unroll 4
    for (int t = 0; t < T_; t++) {
        long o = base + (long)t * N_;
        __half2 p = *reinterpret_cast<const __half2*>(Pp + o);
        float2 pf = __half22float2(p);
        float s = sc[t];
        X0 = (DECF * X0 + pf.x) * s;
        X1 = (DECF * X1 + pf.y) * s;
        __half2 xo = make_half2(__float2half_rn(X0), __float2half_rn(X1));
        *reinterpret_cast<__half2*>(Xp + o) = xo;
    }
}

// fused post-scores: transU (blocks [0,2048)) + decay/mask/fp16 (blocks [2048,4096))
__global__ void post_scores_kernel()
{
    int blk = blockIdx.x;
    int tid = threadIdx.x;
    if (blk < 2048) {
        __shared__ unsigned short tl[32][33];
        int b  = blk >> 6;
        int rem = blk & 63;
        int s0 = (rem & 7) * 32;
        int d0 = (rem >> 3) * 32;
        int tx = tid & 31, ty = tid >> 5;
        const unsigned short* src = reinterpret_cast<const unsigned short*>(g_Uh);
        unsigned short* dst = reinterpret_cast<unsigned short*>(g_UT);
#pragma unroll
        for (int i = ty; i < 32; i += 8)
            tl[i][tx] = src[((long)b * T_ + s0 + i) * D_ + d0 + tx];
        __syncthreads();
#pragma unroll
        for (int i = ty; i < 32; i += 8)
            dst[(long)b * D_ * T_ + (long)(d0 + i) * T_ + s0 + tx] = tl[tx][i];
    } else {
        int m = (blk - 2048) * 4 + (tid >> 6);
        int t = m & (T_ - 1);
        int s0 = (tid & 63) * 4;
        long o = (long)m * T_ + s0;
        const float* S = g_S;
        const long P = (long)B_ * T_ * T_;
        float4 a0 = *reinterpret_cast<const float4*>(S + o);
        float4 a1 = *reinterpret_cast<const float4*>(S + P + o);
        float4 a2 = *reinterpret_cast<const float4*>(S + 2 * P + o);
        float4 a3 = *reinterpret_cast<const float4*>(S + 3 * P + o);
        float vv[4] = {a0.x + a1.x + a2.x + a3.x, a0.y + a1.y + a2.y + a3.y,
                       a0.z + a1.z + a2.z + a3.z, a0.w + a1.w + a2.w + a3.w};
        unsigned short os[4];
#pragma unroll
        for (int j = 0; j < 4; j++) {
            int L = t - (s0 + j);
            float v = (L > 0) ? vv[j] * g_DEC[L] : 0.f;
            os[j] = __half_as_ushort(__float2half_rn(v));
        }
        *reinterpret_cast<ushort4*>(reinterpret_cast<unsigned short*>(g_Sf) + o) =
            make_ushort4(os[0], os[1], os[2], os[3]);
    }
}

// OUT: 0 = fp32, 1 = fp16 single
template <int OUT, int NPART>
__global__ void ln_rows(const float* __restrict__ in, float* __restrict__ outf,
                        unsigned short* __restrict__ oh, float inscale)
{
    int m = blockIdx.x;
    float z = in[(long)m * D_ + threadIdx.x];
#pragma unroll
    for (int p = 1; p < NPART; p++)
        z += in[(long)p * M_ * D_ + (long)m * D_ + threadIdx.x];
    z *= inscale;
    float mean = blockReduceSum256(z) * (1.f / D_);
    float d = z - mean;
    float var = blockReduceSum256(d * d) * (1.f / (D_ - 1));
    float v = d / (sqrtf(var) + EPSF);
    long o = (long)m * D_ + threadIdx.x;
    if (OUT == 1) {
        oh[o] = __half_as_ushort(__float2half_rn(v));
    } else {
        outf[o] = v;
    }
}

// ---------------- launch ----------------
extern "C" void kernel_launch(void* const* d_in, const int* in_sizes, int n_in,
                              void* d_out, int out_size)
{
    (void)in_sizes; (void)n_in; (void)out_size;
    const int*   idx  = (const int*)d_in[0];
    const float* temb = (const float*)d_in[1];
    const float* E    = (const float*)d_in[2];
    const float* Dx   = (const float*)d_in[3];
    const float* Dy   = (const float*)d_in[4];
    float* out = (float*)d_out;

    float *pS, *pA, *pO;
    __half *pVf, *pDxH, *pDyH, *pEH, *pUT, *pSf, *pAf, *pXf, *pYf;
    cudaGetSymbolAddress((void**)&pS,  g_S);
    cudaGetSymbolAddress((void**)&pA,  g_A);
    cudaGetSymbolAddress((void**)&pO,  g_O);
    cudaGetSymbolAddress((void**)&pVf, g_Vf);
    cudaGetSymbolAddress((void**)&pDxH, g_DxH);
    cudaGetSymbolAddress((void**)&pDyH, g_DyH);
    cudaGetSymbolAddress((void**)&pEH, g_EH);
    cudaGetSymbolAddress((void**)&pUT, g_UT);
    cudaGetSymbolAddress((void**)&pSf, g_Sf);
    cudaGetSymbolAddress((void**)&pAf, g_Af);
    cudaGetSymbolAddress((void**)&pXf, g_Xf);
    cudaGetSymbolAddress((void**)&pYf, g_Yf);

    cudaFuncSetAttribute(mma_nt<EPI_RELUH>,
                         cudaFuncAttributeMaxDynamicSharedMemorySize, SMEM_SZ);
    cudaFuncSetAttribute(mma_nt<EPI_NONE>,
                         cudaFuncAttributeMaxDynamicSharedMemorySize, SMEM_SZ);
    cudaFuncSetAttribute(mma_nt<EPI_RELUMULX>,
                         cudaFuncAttributeMaxDynamicSharedMemorySize, SMEM_SZ);
    cudaFuncSetAttribute(mma_sk,
                         cudaFuncAttributeMaxDynamicSharedMemorySize, SK_SMEM);
    cudaFuncSetAttribute(mma_a,
                         cudaFuncAttributeMaxDynamicSharedMemorySize, AK_SMEM);

    // fused conversions + gather + U-LN (+g_DEC, +g_CS zero)
    conv_gather_uln<<<3072 + M_ / 4 + M_, 256>>>(Dx, Dy, E, temb, idx);

    // G1 (fp16): 256*P = relu((16v) @ (16Dx)^T) -> g_Yf, row-sum -> g_CS
    mma_nt<EPI_RELUH><<<dim3(N_ / 256, M_ / 128, 1), 256, SMEM_SZ>>>(
        pVf, pDxH, nullptr, pYf, nullptr,
        N_, D_, D_, 0, 0, 0, 0, 1);

    screc_kernel<<<1, 256>>>();
    // x scan: half2, 2 independent chains per thread
    xrecur_kernel<<<dim3(N_ / 512, B_, 1), 256>>>();

    // scores (65536*raw, split-K x4, triangular skip, fp16)
    mma_sk<<<dim3(T_ / 128, T_ / 128, 4 * B_), 256, SK_SMEM>>>(pXf, pS, N_ / 4);

    // transU + decay/mask -> fp16 S'
    post_scores_kernel<<<2048 + M_ / 4, 256>>>();

    // 256*a* = S' @ UT (HMMA)
    mma_a<<<dim3(D_ / 128, T_ / 128, B_), 256, AK_SMEM>>>(pSf, pUT, pA);

    // a* <- LN(a*) with exact 1/256 unscale -> fp16
    ln_rows<1, 1><<<M_, 256>>>(pA, nullptr, (unsigned short*)pAf, 1.f / 256.f);

    // G2 (fp16): 1024y = relu(LN(a*) @ (64Dy)^T) * (256x) / 16 -> g_Yf
    mma_nt<EPI_RELUMULX><<<dim3(N_ / 256, M_ / 128, 1), 256, SMEM_SZ>>>(
        pAf, pDyH, nullptr, pYf, pXf,
        N_, D_, D_, 0, 0, 0, 0, 1);

    // G3 (fp16, split-K x2): o_p = (1024y) @ (64E)^T -> g_O partials (65536*o)
    mma_nt<EPI_NONE><<<dim3(D_ / 256, M_ / 128, 2), 256, SMEM_SZ>>>(
        pYf, pEH, pO, nullptr, nullptr,
        D_, N_, N_ / 2, 0, 0, 0, (long)M_ * D_, 1);

    // out = LN((sum of 2 partials) / 65536)
    ln_rows<0, 2><<<M_, 256>>>(pO, out, nullptr, 1.f / 65536.f);
}